// round 1
// baseline (speedup 1.0000x reference)
#include <cuda_runtime.h>
#include <math.h>

#define BATCH 8
#define SEQL 1024
#define DMODEL 512
#define NHEAD 8
#define DHEAD 64
#define DFF 2048
#define NLAYER 6
#define BL (BATCH * SEQL)   // 8192

// ---------------- scratch (device globals: no allocs allowed) -------------
__device__ float g_x[BL * DMODEL];
__device__ float g_h[BL * DMODEL];
__device__ float g_q[BL * DMODEL];
__device__ float g_k[BL * DMODEL];
__device__ float g_v[BL * DMODEL];
__device__ float g_o[BL * DMODEL];
__device__ float g_f[BL * DFF];

// ---------------- positional embedding + add ------------------------------
__global__ void k_pos(const float* __restrict__ xin, float* __restrict__ xout) {
    int idx = blockIdx.x * 256 + threadIdx.x;
    if (idx >= BL * DMODEL) return;
    int d = idx % DMODEL;
    int l = (idx / DMODEL) % SEQL;
    int half = DMODEL / 2;
    int i = (d < half) ? d : d - half;
    float inv = powf(10000.0f, -2.0f * (float)i / (float)DMODEL);
    float ang = (float)l * inv;
    float pe = (d < half) ? sinf(ang) : cosf(ang);
    xout[idx] = xin[idx] + pe;
}

// ---------------- layernorm (one row per block, 128 thr, D=512) -----------
__global__ void __launch_bounds__(128) k_ln(const float* __restrict__ x,
                                            const float* __restrict__ g,
                                            const float* __restrict__ b,
                                            float* __restrict__ out) {
    int row = blockIdx.x;
    int tid = threadIdx.x;
    const float4* xr = (const float4*)(x + (size_t)row * DMODEL);
    float4 v = xr[tid];
    __shared__ float sh[4];

    float s = v.x + v.y + v.z + v.w;
    for (int o = 16; o; o >>= 1) s += __shfl_xor_sync(0xffffffffu, s, o);
    if ((tid & 31) == 0) sh[tid >> 5] = s;
    __syncthreads();
    float mean = (sh[0] + sh[1] + sh[2] + sh[3]) * (1.0f / DMODEL);
    __syncthreads();

    float dx0 = v.x - mean, dx1 = v.y - mean, dx2 = v.z - mean, dx3 = v.w - mean;
    float s2 = dx0 * dx0 + dx1 * dx1 + dx2 * dx2 + dx3 * dx3;
    for (int o = 16; o; o >>= 1) s2 += __shfl_xor_sync(0xffffffffu, s2, o);
    if ((tid & 31) == 0) sh[tid >> 5] = s2;
    __syncthreads();
    float var = (sh[0] + sh[1] + sh[2] + sh[3]) * (1.0f / DMODEL);
    float r = rsqrtf(var + 1e-3f);

    float4 gg = ((const float4*)g)[tid];
    float4 bb = ((const float4*)b)[tid];
    float4 o4;
    o4.x = dx0 * r * gg.x + bb.x;
    o4.y = dx1 * r * gg.y + bb.y;
    o4.z = dx2 * r * gg.z + bb.z;
    o4.w = dx3 * r * gg.w + bb.w;
    ((float4*)(out + (size_t)row * DMODEL))[tid] = o4;
}

// ---------------- tiled fp32 GEMM: C = A[MxK] @ W[KxN] (+bias)(+res)(relu)
#define BM 128
#define BN 64
#define BK 16

template <bool BIAS, bool RELU, bool RES>
__global__ void __launch_bounds__(256) k_gemm(const float* __restrict__ A,
                                              const float* __restrict__ W,
                                              const float* __restrict__ bias,
                                              const float* __restrict__ res,
                                              float* __restrict__ C,
                                              int M, int N, int K) {
    __shared__ float As[BK][BM + 4];
    __shared__ float Ws[BK][BN + 4];

    int tid = threadIdx.x;
    int tx = tid & 15;   // N dir
    int ty = tid >> 4;   // M dir
    int m0 = blockIdx.y * BM;
    int n0 = blockIdx.x * BN;

    float acc[8][4];
#pragma unroll
    for (int i = 0; i < 8; i++)
#pragma unroll
        for (int j = 0; j < 4; j++) acc[i][j] = 0.0f;

    int ar0 = tid >> 2;            // 0..63
    int ak0 = (tid & 3) * 4;       // 0,4,8,12
    const float* Aptr = A + (size_t)(m0 + ar0) * K + ak0;
    int wr = tid >> 4;             // 0..15 (k row)
    int wc = (tid & 15) * 4;       // 0..60
    const float* Wptr = W + (size_t)wr * N + n0 + wc;

    for (int kt = 0; kt < K; kt += BK) {
        float4 a0 = *(const float4*)(Aptr + kt);
        float4 a1 = *(const float4*)(Aptr + (size_t)64 * K + kt);
        float4 w0 = *(const float4*)(Wptr + (size_t)kt * N);

        As[ak0 + 0][ar0] = a0.x;
        As[ak0 + 1][ar0] = a0.y;
        As[ak0 + 2][ar0] = a0.z;
        As[ak0 + 3][ar0] = a0.w;
        As[ak0 + 0][ar0 + 64] = a1.x;
        As[ak0 + 1][ar0 + 64] = a1.y;
        As[ak0 + 2][ar0 + 64] = a1.z;
        As[ak0 + 3][ar0 + 64] = a1.w;
        *(float4*)&Ws[wr][wc] = w0;
        __syncthreads();

#pragma unroll
        for (int kk = 0; kk < BK; kk++) {
            float4 av0 = *(const float4*)&As[kk][ty * 8];
            float4 av1 = *(const float4*)&As[kk][ty * 8 + 4];
            float4 wv = *(const float4*)&Ws[kk][tx * 4];
            float a[8] = {av0.x, av0.y, av0.z, av0.w, av1.x, av1.y, av1.z, av1.w};
            float w[4] = {wv.x, wv.y, wv.z, wv.w};
#pragma unroll
            for (int i = 0; i < 8; i++)
#pragma unroll
                for (int j = 0; j < 4; j++)
                    acc[i][j] = fmaf(a[i], w[j], acc[i][j]);
        }
        __syncthreads();
    }

    float bb[4] = {0.f, 0.f, 0.f, 0.f};
    if (BIAS) {
#pragma unroll
        for (int j = 0; j < 4; j++) bb[j] = bias[n0 + tx * 4 + j];
    }
#pragma unroll
    for (int i = 0; i < 8; i++) {
        int m = m0 + ty * 8 + i;
        size_t off = (size_t)m * N + n0 + tx * 4;
        float4 rv = make_float4(0.f, 0.f, 0.f, 0.f);
        if (RES) rv = *(const float4*)(res + off);
        float o0 = acc[i][0] + bb[0] + rv.x;
        float o1 = acc[i][1] + bb[1] + rv.y;
        float o2 = acc[i][2] + bb[2] + rv.z;
        float o3 = acc[i][3] + bb[3] + rv.w;
        if (RELU) {
            o0 = fmaxf(o0, 0.f); o1 = fmaxf(o1, 0.f);
            o2 = fmaxf(o2, 0.f); o3 = fmaxf(o3, 0.f);
        }
        *(float4*)(C + off) = make_float4(o0, o1, o2, o3);
    }
}

// ---------------- flash attention, 64x64 tiles, online softmax -------------
#define AT 64
#define ATP 68
#define ATT_SMEM ((4 * AT * ATP + 3 * AT) * 4)

__global__ void __launch_bounds__(256) k_attn(const float* __restrict__ Q,
                                              const float* __restrict__ Kg,
                                              const float* __restrict__ Vg,
                                              const int* __restrict__ lengths,
                                              float* __restrict__ O) {
    extern __shared__ float sm[];
    float* Qt = sm;                 // [DH][AT]  Qt[dh][r], pre-scaled
    float* Kt = Qt + AT * ATP;      // [DH][AT]  Kt[dh][c]
    float* Vs = Kt + AT * ATP;      // [AT][DH]  Vs[c][dh]
    float* St = Vs + AT * ATP;      // [AT][AT]  St[c][r]  (scores -> probs)
    float* rowm = St + AT * ATP;    // [AT]
    float* rowl = rowm + AT;        // [AT]
    float* rowa = rowl + AT;        // [AT]

    int b = blockIdx.z, h = blockIdx.y, qt = blockIdx.x;
    int len = lengths[b];
    int tid = threadIdx.x;
    int tx = tid & 15, ty = tid >> 4;

    // load Q tile transposed + scaled (scale = 1/sqrt(64) = 0.125)
    const float* qbase = Q + ((size_t)(b * SEQL + qt * AT)) * DMODEL + h * DHEAD;
#pragma unroll
    for (int it = 0; it < 4; it++) {
        int f = tid + 256 * it;
        int r = f >> 4;
        int c4 = (f & 15) * 4;
        float4 v = *(const float4*)(qbase + (size_t)r * DMODEL + c4);
        Qt[(c4 + 0) * ATP + r] = v.x * 0.125f;
        Qt[(c4 + 1) * ATP + r] = v.y * 0.125f;
        Qt[(c4 + 2) * ATP + r] = v.z * 0.125f;
        Qt[(c4 + 3) * ATP + r] = v.w * 0.125f;
    }
    if (tid < AT) { rowm[tid] = -3.0e38f; rowl[tid] = 0.0f; }

    float oacc[4][4];
#pragma unroll
    for (int i = 0; i < 4; i++)
#pragma unroll
        for (int j = 0; j < 4; j++) oacc[i][j] = 0.0f;

    int nkt = (len + AT - 1) / AT;   // fully-masked tiles contribute exactly 0
    for (int kt = 0; kt < nkt; kt++) {
        __syncthreads();
        const float* kbase = Kg + ((size_t)(b * SEQL + kt * AT)) * DMODEL + h * DHEAD;
        const float* vbase = Vg + ((size_t)(b * SEQL + kt * AT)) * DMODEL + h * DHEAD;
#pragma unroll
        for (int it = 0; it < 4; it++) {
            int f = tid + 256 * it;
            int r = f >> 4;
            int c4 = (f & 15) * 4;
            float4 kv = *(const float4*)(kbase + (size_t)r * DMODEL + c4);
            Kt[(c4 + 0) * ATP + r] = kv.x;
            Kt[(c4 + 1) * ATP + r] = kv.y;
            Kt[(c4 + 2) * ATP + r] = kv.z;
            Kt[(c4 + 3) * ATP + r] = kv.w;
            float4 vv = *(const float4*)(vbase + (size_t)r * DMODEL + c4);
            *(float4*)&Vs[r * ATP + c4] = vv;
        }
        __syncthreads();

        // S = (Q*scale) K^T : thread computes rows ty*4+i, cols tx*4+j
        float s[4][4];
#pragma unroll
        for (int i = 0; i < 4; i++)
#pragma unroll
            for (int j = 0; j < 4; j++) s[i][j] = 0.0f;
#pragma unroll
        for (int kk = 0; kk < AT; kk++) {
            float4 qa = *(const float4*)&Qt[kk * ATP + ty * 4];
            float4 kb = *(const float4*)&Kt[kk * ATP + tx * 4];
            float aq[4] = {qa.x, qa.y, qa.z, qa.w};
            float ak[4] = {kb.x, kb.y, kb.z, kb.w};
#pragma unroll
            for (int i = 0; i < 4; i++)
#pragma unroll
                for (int j = 0; j < 4; j++)
                    s[i][j] = fmaf(aq[i], ak[j], s[i][j]);
        }
#pragma unroll
        for (int j = 0; j < 4; j++)
            *(float4*)&St[(tx * 4 + j) * ATP + ty * 4] =
                make_float4(s[0][j], s[1][j], s[2][j], s[3][j]);
        __syncthreads();

        // online softmax: 64 rows x 4 threads, each thread 16 contiguous cols
        {
            int rr = tid >> 2, tt = tid & 3;
            float p[16];
            float mloc = -3.0e38f;
            int kb0 = kt * AT;
#pragma unroll
            for (int u = 0; u < 16; u++) {
                int c = tt * 16 + u;
                float sv = St[c * ATP + rr];
                if (kb0 + c >= len) sv += -1e9f;    // reference mask bias
                p[u] = sv;
                mloc = fmaxf(mloc, sv);
            }
            mloc = fmaxf(mloc, __shfl_xor_sync(0xffffffffu, mloc, 1));
            mloc = fmaxf(mloc, __shfl_xor_sync(0xffffffffu, mloc, 2));
            float mold = rowm[rr];
            float mnew = fmaxf(mold, mloc);
            float lsum = 0.0f;
#pragma unroll
            for (int u = 0; u < 16; u++) {
                int c = tt * 16 + u;
                float pv = __expf(p[u] - mnew);
                lsum += pv;
                St[c * ATP + rr] = pv;
            }
            lsum += __shfl_xor_sync(0xffffffffu, lsum, 1);
            lsum += __shfl_xor_sync(0xffffffffu, lsum, 2);
            if (tt == 0) {
                float a = __expf(mold - mnew);
                rowm[rr] = mnew;
                rowl[rr] = rowl[rr] * a + lsum;
                rowa[rr] = a;
            }
        }
        __syncthreads();

        // O = O*alpha + P V
        float al[4];
#pragma unroll
        for (int i = 0; i < 4; i++) al[i] = rowa[ty * 4 + i];
#pragma unroll
        for (int i = 0; i < 4; i++)
#pragma unroll
            for (int j = 0; j < 4; j++) oacc[i][j] *= al[i];
#pragma unroll
        for (int c = 0; c < AT; c++) {
            float4 pv = *(const float4*)&St[c * ATP + ty * 4];
            float4 vv = *(const float4*)&Vs[c * ATP + tx * 4];
            float ap[4] = {pv.x, pv.y, pv.z, pv.w};
            float av[4] = {vv.x, vv.y, vv.z, vv.w};
#pragma unroll
            for (int i = 0; i < 4; i++)
#pragma unroll
                for (int j = 0; j < 4; j++)
                    oacc[i][j] = fmaf(ap[i], av[j], oacc[i][j]);
        }
    }

    float linv[4];
#pragma unroll
    for (int i = 0; i < 4; i++) linv[i] = 1.0f / rowl[ty * 4 + i];
    float* obase = O + ((size_t)(b * SEQL + qt * AT)) * DMODEL + h * DHEAD;
#pragma unroll
    for (int i = 0; i < 4; i++) {
        *(float4*)(obase + (size_t)(ty * 4 + i) * DMODEL + tx * 4) =
            make_float4(oacc[i][0] * linv[i], oacc[i][1] * linv[i],
                        oacc[i][2] * linv[i], oacc[i][3] * linv[i]);
    }
}

// ---------------- orchestration -------------------------------------------
extern "C" void kernel_launch(void* const* d_in, const int* in_sizes, int n_in,
                              void* d_out, int out_size) {
    (void)in_sizes; (void)n_in; (void)out_size;
    const float* x_in   = (const float*)d_in[0];
    const int*   lengths = (const int*)d_in[1];
    const float* Wq = (const float*)d_in[2];
    const float* Wk = (const float*)d_in[3];
    const float* Wv = (const float*)d_in[4];
    const float* Wo = (const float*)d_in[5];
    const float* ln1g = (const float*)d_in[6];
    const float* ln1b = (const float*)d_in[7];
    const float* ln2g = (const float*)d_in[8];
    const float* ln2b = (const float*)d_in[9];
    const float* w1 = (const float*)d_in[10];
    const float* b1 = (const float*)d_in[11];
    const float* w2 = (const float*)d_in[12];
    const float* b2 = (const float*)d_in[13];

    float *px, *ph, *pq, *pk, *pv, *po, *pf;
    cudaGetSymbolAddress((void**)&px, g_x);
    cudaGetSymbolAddress((void**)&ph, g_h);
    cudaGetSymbolAddress((void**)&pq, g_q);
    cudaGetSymbolAddress((void**)&pk, g_k);
    cudaGetSymbolAddress((void**)&pv, g_v);
    cudaGetSymbolAddress((void**)&po, g_o);
    cudaGetSymbolAddress((void**)&pf, g_f);

    cudaFuncSetAttribute(k_attn, cudaFuncAttributeMaxDynamicSharedMemorySize, ATT_SMEM);

    k_pos<<<(BL * DMODEL) / 256, 256>>>(x_in, px);

    dim3 gD(DMODEL / BN, BL / BM);   // N=512 GEMMs
    dim3 gF(DFF / BN, BL / BM);      // N=2048 GEMM

    for (int layer = 0; layer < NLAYER; layer++) {
        const float* wq = Wq + (size_t)layer * DMODEL * DMODEL;
        const float* wk = Wk + (size_t)layer * DMODEL * DMODEL;
        const float* wv = Wv + (size_t)layer * DMODEL * DMODEL;
        const float* wo = Wo + (size_t)layer * DMODEL * DMODEL;

        k_ln<<<BL, 128>>>(px, ln1g + (size_t)layer * DMODEL, ln1b + (size_t)layer * DMODEL, ph);
        k_gemm<false, false, false><<<gD, 256>>>(ph, wq, nullptr, nullptr, pq, BL, DMODEL, DMODEL);
        k_gemm<false, false, false><<<gD, 256>>>(ph, wk, nullptr, nullptr, pk, BL, DMODEL, DMODEL);
        k_gemm<false, false, false><<<gD, 256>>>(ph, wv, nullptr, nullptr, pv, BL, DMODEL, DMODEL);
        k_attn<<<dim3(SEQL / AT, NHEAD, BATCH), 256, ATT_SMEM>>>(pq, pk, pv, lengths, po);
        k_gemm<false, false, true><<<gD, 256>>>(po, wo, nullptr, px, px, BL, DMODEL, DMODEL);

        k_ln<<<BL, 128>>>(px, ln2g + (size_t)layer * DMODEL, ln2b + (size_t)layer * DMODEL, ph);
        k_gemm<true, true, false><<<gF, 256>>>(ph, w1 + (size_t)layer * DMODEL * DFF,
                                               b1 + (size_t)layer * DFF, nullptr, pf,
                                               BL, DFF, DMODEL);
        float* dst = (layer == NLAYER - 1) ? (float*)d_out : px;
        k_gemm<true, false, true><<<gD, 256>>>(pf, w2 + (size_t)layer * DFF * DMODEL,
                                               b2 + (size_t)layer * DMODEL, px, dst,
                                               BL, DMODEL, DFF);
    }
}

// round 2
// speedup vs baseline: 2.0681x; 2.0681x over previous
#include <cuda_runtime.h>
#include <cuda_bf16.h>
#include <math.h>
#include <stdint.h>

#define BATCH 8
#define SEQL 1024
#define DMODEL 512
#define NHEAD 8
#define DHEAD 64
#define DFF 2048
#define NLAYER 6
#define BL (BATCH * SEQL)   // 8192

typedef __nv_bfloat16 bf16;

// ---------------- scratch (device globals: no allocs allowed) -------------
__device__ __align__(128) float g_x[BL * DMODEL];
__device__ __align__(128) float g_q[BL * DMODEL];
__device__ __align__(128) float g_k[BL * DMODEL];
__device__ __align__(128) float g_v[BL * DMODEL];
__device__ __align__(128) float g_o[BL * DMODEL];
__device__ __align__(128) bf16  g_hh[BL * DMODEL];
__device__ __align__(128) bf16  g_hl[BL * DMODEL];
__device__ __align__(128) bf16  g_fh[BL * DFF];
__device__ __align__(128) bf16  g_fl[BL * DFF];
#define WSZ_D  (NLAYER * DMODEL * DMODEL)   // 1572864
#define WSZ_F  (NLAYER * DMODEL * DFF)      // 6291456
#define WTOT   (4 * WSZ_D + 2 * WSZ_F)
__device__ __align__(128) bf16  g_wh[WTOT];
__device__ __align__(128) bf16  g_wl[WTOT];
#define OFF_WQ 0
#define OFF_WK (1 * WSZ_D)
#define OFF_WV (2 * WSZ_D)
#define OFF_WO (3 * WSZ_D)
#define OFF_W1 (4 * WSZ_D)
#define OFF_W2 (4 * WSZ_D + WSZ_F)

// ---------------- positional embedding + add ------------------------------
__global__ void k_pos(const float* __restrict__ xin, float* __restrict__ xout) {
    int idx = blockIdx.x * 256 + threadIdx.x;
    if (idx >= BL * DMODEL) return;
    int d = idx % DMODEL;
    int l = (idx / DMODEL) % SEQL;
    int half = DMODEL / 2;
    int i = (d < half) ? d : d - half;
    float inv = powf(10000.0f, -2.0f * (float)i / (float)DMODEL);
    float ang = (float)l * inv;
    float pe = (d < half) ? sinf(ang) : cosf(ang);
    xout[idx] = xin[idx] + pe;
}

// ---------------- fp32 -> (hi,lo) bf16 split ------------------------------
__global__ void k_split(const float* __restrict__ x, bf16* __restrict__ hi,
                        bf16* __restrict__ lo, int n) {
    int i = (blockIdx.x * 256 + threadIdx.x) * 4;
    if (i >= n) return;
    float4 v = *(const float4*)(x + i);
    bf16 h0 = __float2bfloat16_rn(v.x);
    bf16 h1 = __float2bfloat16_rn(v.y);
    bf16 h2 = __float2bfloat16_rn(v.z);
    bf16 h3 = __float2bfloat16_rn(v.w);
    bf16 l0 = __float2bfloat16_rn(v.x - __bfloat162float(h0));
    bf16 l1 = __float2bfloat16_rn(v.y - __bfloat162float(h1));
    bf16 l2 = __float2bfloat16_rn(v.z - __bfloat162float(h2));
    bf16 l3 = __float2bfloat16_rn(v.w - __bfloat162float(h3));
    __nv_bfloat162* hp = (__nv_bfloat162*)(hi + i);
    __nv_bfloat162* lp = (__nv_bfloat162*)(lo + i);
    hp[0] = __nv_bfloat162(h0, h1); hp[1] = __nv_bfloat162(h2, h3);
    lp[0] = __nv_bfloat162(l0, l1); lp[1] = __nv_bfloat162(l2, l3);
}

// ---------------- layernorm -> split bf16 output --------------------------
__global__ void __launch_bounds__(128) k_ln(const float* __restrict__ x,
                                            const float* __restrict__ g,
                                            const float* __restrict__ b,
                                            bf16* __restrict__ ohi,
                                            bf16* __restrict__ olo) {
    int row = blockIdx.x;
    int tid = threadIdx.x;
    const float4* xr = (const float4*)(x + (size_t)row * DMODEL);
    float4 v = xr[tid];
    __shared__ float sh[4];

    float s = v.x + v.y + v.z + v.w;
    for (int o = 16; o; o >>= 1) s += __shfl_xor_sync(0xffffffffu, s, o);
    if ((tid & 31) == 0) sh[tid >> 5] = s;
    __syncthreads();
    float mean = (sh[0] + sh[1] + sh[2] + sh[3]) * (1.0f / DMODEL);
    __syncthreads();

    float dx0 = v.x - mean, dx1 = v.y - mean, dx2 = v.z - mean, dx3 = v.w - mean;
    float s2 = dx0 * dx0 + dx1 * dx1 + dx2 * dx2 + dx3 * dx3;
    for (int o = 16; o; o >>= 1) s2 += __shfl_xor_sync(0xffffffffu, s2, o);
    if ((tid & 31) == 0) sh[tid >> 5] = s2;
    __syncthreads();
    float var = (sh[0] + sh[1] + sh[2] + sh[3]) * (1.0f / DMODEL);
    float r = rsqrtf(var + 1e-3f);

    float4 gg = ((const float4*)g)[tid];
    float4 bb = ((const float4*)b)[tid];
    float o0 = dx0 * r * gg.x + bb.x;
    float o1 = dx1 * r * gg.y + bb.y;
    float o2 = dx2 * r * gg.z + bb.z;
    float o3 = dx3 * r * gg.w + bb.w;

    bf16 h0 = __float2bfloat16_rn(o0), h1 = __float2bfloat16_rn(o1);
    bf16 h2 = __float2bfloat16_rn(o2), h3 = __float2bfloat16_rn(o3);
    bf16 l0 = __float2bfloat16_rn(o0 - __bfloat162float(h0));
    bf16 l1 = __float2bfloat16_rn(o1 - __bfloat162float(h1));
    bf16 l2 = __float2bfloat16_rn(o2 - __bfloat162float(h2));
    bf16 l3 = __float2bfloat16_rn(o3 - __bfloat162float(h3));
    size_t off = (size_t)row * DMODEL + tid * 4;
    __nv_bfloat162* hp = (__nv_bfloat162*)(ohi + off);
    __nv_bfloat162* lp = (__nv_bfloat162*)(olo + off);
    hp[0] = __nv_bfloat162(h0, h1); hp[1] = __nv_bfloat162(h2, h3);
    lp[0] = __nv_bfloat162(l0, l1); lp[1] = __nv_bfloat162(l2, l3);
}

// ---------------- bf16x3 tensor-core GEMM ---------------------------------
// C[M,N] = A[M,K] @ B[K,N] computed as Ahi*Bhi + Ahi*Blo + Alo*Bhi (fp32 acc)
#define GBM 128
#define GBN 128
#define GBK 64
#define STAGE_ELEMS (2 * GBM * GBK + 2 * GBK * GBN)   // 32768 bf16
#define SOFF_AH 0
#define SOFF_AL (GBM * GBK)
#define SOFF_BH (2 * GBM * GBK)
#define SOFF_BL (2 * GBM * GBK + GBK * GBN)
#define GSMEM (2 * STAGE_ELEMS * 2)                   // 131072 bytes

__device__ __forceinline__ void cp16(uint32_t s, const void* g) {
    asm volatile("cp.async.cg.shared.global [%0], [%1], 16;\n" :: "r"(s), "l"(g));
}
__device__ __forceinline__ void cp_commit() {
    asm volatile("cp.async.commit_group;\n" ::: "memory");
}
template <int N_>
__device__ __forceinline__ void cp_wait() {
    asm volatile("cp.async.wait_group %0;\n" :: "n"(N_) : "memory");
}
__device__ __forceinline__ void ldsm4(uint32_t* r, uint32_t addr) {
    asm volatile("ldmatrix.sync.aligned.m8n8.x4.shared.b16 {%0,%1,%2,%3}, [%4];"
                 : "=r"(r[0]), "=r"(r[1]), "=r"(r[2]), "=r"(r[3]) : "r"(addr));
}
__device__ __forceinline__ void ldsm4t(uint32_t& r0, uint32_t& r1, uint32_t& r2,
                                       uint32_t& r3, uint32_t addr) {
    asm volatile("ldmatrix.sync.aligned.m8n8.x4.trans.shared.b16 {%0,%1,%2,%3}, [%4];"
                 : "=r"(r0), "=r"(r1), "=r"(r2), "=r"(r3) : "r"(addr));
}
__device__ __forceinline__ void mma16816(float* c, const uint32_t* a, const uint32_t* b) {
    asm volatile(
        "mma.sync.aligned.m16n8k16.row.col.f32.bf16.bf16.f32 "
        "{%0,%1,%2,%3}, {%4,%5,%6,%7}, {%8,%9}, {%0,%1,%2,%3};"
        : "+f"(c[0]), "+f"(c[1]), "+f"(c[2]), "+f"(c[3])
        : "r"(a[0]), "r"(a[1]), "r"(a[2]), "r"(a[3]), "r"(b[0]), "r"(b[1]));
}

template <bool BIAS, bool RELU, bool RES, bool SPLIT>
__global__ void __launch_bounds__(256, 1) k_mm(
    const bf16* __restrict__ Ah, const bf16* __restrict__ Al,
    const bf16* __restrict__ Bh, const bf16* __restrict__ Bl,
    const float* __restrict__ bias, const float* __restrict__ res,
    float* __restrict__ Cf, bf16* __restrict__ Ch, bf16* __restrict__ Cl,
    int M, int N, int K) {
    extern __shared__ bf16 sm[];
    int tid = threadIdx.x;
    int lane = tid & 31, wid = tid >> 5;
    int wm = wid >> 2, wn = wid & 3;
    int m0 = blockIdx.y * GBM, n0 = blockIdx.x * GBN;
    uint32_t smbase = (uint32_t)__cvta_generic_to_shared(sm);

    float acc[4][4][4];
#pragma unroll
    for (int i = 0; i < 4; i++)
#pragma unroll
        for (int j = 0; j < 4; j++)
#pragma unroll
            for (int q = 0; q < 4; q++) acc[i][j][q] = 0.0f;

    int nk = K / GBK;

    auto load_stage = [&](int kt, int stg) {
        uint32_t sb = smbase + (uint32_t)stg * STAGE_ELEMS * 2;
#pragma unroll
        for (int p = 0; p < 4; p++) {
            int f = p * 256 + tid;
            int m = f >> 3, c = f & 7;
            uint32_t dst = (uint32_t)(m * GBK + ((c ^ (m & 7)) << 3));
            size_t src = (size_t)(m0 + m) * K + kt * GBK + (c << 3);
            cp16(sb + (SOFF_AH + dst) * 2, Ah + src);
            cp16(sb + (SOFF_AL + dst) * 2, Al + src);
        }
#pragma unroll
        for (int p = 0; p < 4; p++) {
            int f = p * 256 + tid;
            int k = f >> 4, c = f & 15;
            int cs = (c & 8) | ((c ^ (k & 7)) & 7);
            uint32_t dst = (uint32_t)(k * GBN + (cs << 3));
            size_t src = (size_t)(kt * GBK + k) * N + n0 + (c << 3);
            cp16(sb + (SOFF_BH + dst) * 2, Bh + src);
            cp16(sb + (SOFF_BL + dst) * 2, Bl + src);
        }
        cp_commit();
    };

    load_stage(0, 0);

    for (int kt = 0; kt < nk; kt++) {
        if (kt + 1 < nk) {
            load_stage(kt + 1, (kt + 1) & 1);
            cp_wait<1>();
        } else {
            cp_wait<0>();
        }
        __syncthreads();
        uint32_t sb = smbase + (uint32_t)(kt & 1) * STAGE_ELEMS * 2;

#pragma unroll
        for (int ks = 0; ks < GBK / 16; ks++) {
            uint32_t ah[4][4], al[4][4];
#pragma unroll
            for (int mt = 0; mt < 4; mt++) {
                int row = wm * 64 + mt * 16 + (lane & 15);
                int kc = ks * 2 + (lane >> 4);
                uint32_t off = (uint32_t)(row * GBK + ((kc ^ (row & 7)) << 3)) * 2;
                ldsm4(ah[mt], sb + SOFF_AH * 2 + off);
                ldsm4(al[mt], sb + SOFF_AL * 2 + off);
            }
            uint32_t bh[4][2], bl[4][2];
#pragma unroll
            for (int np = 0; np < 2; np++) {
                int krow = ks * 16 + (lane & 15);
                int nc = wn * 4 + np * 2 + (lane >> 4);
                int ncs = (nc & 8) | ((nc ^ (krow & 7)) & 7);
                uint32_t off = (uint32_t)(krow * GBN + (ncs << 3)) * 2;
                uint32_t r0, r1, r2, r3;
                ldsm4t(r0, r1, r2, r3, sb + SOFF_BH * 2 + off);
                bh[np * 2][0] = r0; bh[np * 2][1] = r1;
                bh[np * 2 + 1][0] = r2; bh[np * 2 + 1][1] = r3;
                ldsm4t(r0, r1, r2, r3, sb + SOFF_BL * 2 + off);
                bl[np * 2][0] = r0; bl[np * 2][1] = r1;
                bl[np * 2 + 1][0] = r2; bl[np * 2 + 1][1] = r3;
            }
#pragma unroll
            for (int mt = 0; mt < 4; mt++)
#pragma unroll
                for (int nt = 0; nt < 4; nt++) {
                    mma16816(acc[mt][nt], ah[mt], bh[nt]);
                    mma16816(acc[mt][nt], ah[mt], bl[nt]);
                    mma16816(acc[mt][nt], al[mt], bh[nt]);
                }
        }
        __syncthreads();
    }

    // epilogue
#pragma unroll
    for (int mt = 0; mt < 4; mt++)
#pragma unroll
        for (int nt = 0; nt < 4; nt++) {
            int rbase = m0 + wm * 64 + mt * 16 + (lane >> 2);
            int cbase = n0 + wn * 32 + nt * 8 + (lane & 3) * 2;
#pragma unroll
            for (int half = 0; half < 2; half++) {
                int r = rbase + half * 8;
                float c0 = acc[mt][nt][half * 2 + 0];
                float c1 = acc[mt][nt][half * 2 + 1];
                size_t off = (size_t)r * N + cbase;
                if (BIAS) { c0 += bias[cbase]; c1 += bias[cbase + 1]; }
                if (RES)  { float2 rv = *(const float2*)(res + off); c0 += rv.x; c1 += rv.y; }
                if (RELU) { c0 = fmaxf(c0, 0.f); c1 = fmaxf(c1, 0.f); }
                if (SPLIT) {
                    bf16 h0 = __float2bfloat16_rn(c0), h1 = __float2bfloat16_rn(c1);
                    bf16 l0 = __float2bfloat16_rn(c0 - __bfloat162float(h0));
                    bf16 l1 = __float2bfloat16_rn(c1 - __bfloat162float(h1));
                    *(__nv_bfloat162*)(Ch + off) = __nv_bfloat162(h0, h1);
                    *(__nv_bfloat162*)(Cl + off) = __nv_bfloat162(l0, l1);
                } else {
                    *(float2*)(Cf + off) = make_float2(c0, c1);
                }
            }
        }
}

// ---------------- flash attention, 64x64 tiles (fp32 SIMT) -----------------
#define AT 64
#define ATP 68
#define ATT_SMEM ((4 * AT * ATP + 3 * AT) * 4)

__global__ void __launch_bounds__(256) k_attn(const float* __restrict__ Q,
                                              const float* __restrict__ Kg,
                                              const float* __restrict__ Vg,
                                              const int* __restrict__ lengths,
                                              float* __restrict__ O) {
    extern __shared__ float smf[];
    float* Qt = smf;
    float* Kt = Qt + AT * ATP;
    float* Vs = Kt + AT * ATP;
    float* St = Vs + AT * ATP;
    float* rowm = St + AT * ATP;
    float* rowl = rowm + AT;
    float* rowa = rowl + AT;

    int b = blockIdx.z, h = blockIdx.y, qt = blockIdx.x;
    int len = lengths[b];
    int tid = threadIdx.x;
    int tx = tid & 15, ty = tid >> 4;

    const float* qbase = Q + ((size_t)(b * SEQL + qt * AT)) * DMODEL + h * DHEAD;
#pragma unroll
    for (int it = 0; it < 4; it++) {
        int f = tid + 256 * it;
        int r = f >> 4;
        int c4 = (f & 15) * 4;
        float4 v = *(const float4*)(qbase + (size_t)r * DMODEL + c4);
        Qt[(c4 + 0) * ATP + r] = v.x * 0.125f;
        Qt[(c4 + 1) * ATP + r] = v.y * 0.125f;
        Qt[(c4 + 2) * ATP + r] = v.z * 0.125f;
        Qt[(c4 + 3) * ATP + r] = v.w * 0.125f;
    }
    if (tid < AT) { rowm[tid] = -3.0e38f; rowl[tid] = 0.0f; }

    float oacc[4][4];
#pragma unroll
    for (int i = 0; i < 4; i++)
#pragma unroll
        for (int j = 0; j < 4; j++) oacc[i][j] = 0.0f;

    int nkt = (len + AT - 1) / AT;
    for (int kt = 0; kt < nkt; kt++) {
        __syncthreads();
        const float* kbase = Kg + ((size_t)(b * SEQL + kt * AT)) * DMODEL + h * DHEAD;
        const float* vbase = Vg + ((size_t)(b * SEQL + kt * AT)) * DMODEL + h * DHEAD;
#pragma unroll
        for (int it = 0; it < 4; it++) {
            int f = tid + 256 * it;
            int r = f >> 4;
            int c4 = (f & 15) * 4;
            float4 kv = *(const float4*)(kbase + (size_t)r * DMODEL + c4);
            Kt[(c4 + 0) * ATP + r] = kv.x;
            Kt[(c4 + 1) * ATP + r] = kv.y;
            Kt[(c4 + 2) * ATP + r] = kv.z;
            Kt[(c4 + 3) * ATP + r] = kv.w;
            float4 vv = *(const float4*)(vbase + (size_t)r * DMODEL + c4);
            *(float4*)&Vs[r * ATP + c4] = vv;
        }
        __syncthreads();

        float s[4][4];
#pragma unroll
        for (int i = 0; i < 4; i++)
#pragma unroll
            for (int j = 0; j < 4; j++) s[i][j] = 0.0f;
#pragma unroll
        for (int kk = 0; kk < AT; kk++) {
            float4 qa = *(const float4*)&Qt[kk * ATP + ty * 4];
            float4 kb = *(const float4*)&Kt[kk * ATP + tx * 4];
            float aq[4] = {qa.x, qa.y, qa.z, qa.w};
            float ak[4] = {kb.x, kb.y, kb.z, kb.w};
#pragma unroll
            for (int i = 0; i < 4; i++)
#pragma unroll
                for (int j = 0; j < 4; j++)
                    s[i][j] = fmaf(aq[i], ak[j], s[i][j]);
        }
#pragma unroll
        for (int j = 0; j < 4; j++)
            *(float4*)&St[(tx * 4 + j) * ATP + ty * 4] =
                make_float4(s[0][j], s[1][j], s[2][j], s[3][j]);
        __syncthreads();

        {
            int rr = tid >> 2, tt = tid & 3;
            float p[16];
            float mloc = -3.0e38f;
            int kb0 = kt * AT;
#pragma unroll
            for (int u = 0; u < 16; u++) {
                int c = tt * 16 + u;
                float sv = St[c * ATP + rr];
                if (kb0 + c >= len) sv += -1e9f;
                p[u] = sv;
                mloc = fmaxf(mloc, sv);
            }
            mloc = fmaxf(mloc, __shfl_xor_sync(0xffffffffu, mloc, 1));
            mloc = fmaxf(mloc, __shfl_xor_sync(0xffffffffu, mloc, 2));
            float mold = rowm[rr];
            float mnew = fmaxf(mold, mloc);
            float lsum = 0.0f;
#pragma unroll
            for (int u = 0; u < 16; u++) {
                int c = tt * 16 + u;
                float pv = __expf(p[u] - mnew);
                lsum += pv;
                St[c * ATP + rr] = pv;
            }
            lsum += __shfl_xor_sync(0xffffffffu, lsum, 1);
            lsum += __shfl_xor_sync(0xffffffffu, lsum, 2);
            if (tt == 0) {
                float a = __expf(mold - mnew);
                rowm[rr] = mnew;
                rowl[rr] = rowl[rr] * a + lsum;
                rowa[rr] = a;
            }
        }
        __syncthreads();

        float al[4];
#pragma unroll
        for (int i = 0; i < 4; i++) al[i] = rowa[ty * 4 + i];
#pragma unroll
        for (int i = 0; i < 4; i++)
#pragma unroll
            for (int j = 0; j < 4; j++) oacc[i][j] *= al[i];
#pragma unroll
        for (int c = 0; c < AT; c++) {
            float4 pv = *(const float4*)&St[c * ATP + ty * 4];
            float4 vv = *(const float4*)&Vs[c * ATP + tx * 4];
            float ap[4] = {pv.x, pv.y, pv.z, pv.w};
            float av[4] = {vv.x, vv.y, vv.z, vv.w};
#pragma unroll
            for (int i = 0; i < 4; i++)
#pragma unroll
                for (int j = 0; j < 4; j++)
                    oacc[i][j] = fmaf(ap[i], av[j], oacc[i][j]);
        }
    }

    float linv[4];
#pragma unroll
    for (int i = 0; i < 4; i++) linv[i] = 1.0f / rowl[ty * 4 + i];
    float* obase = O + ((size_t)(b * SEQL + qt * AT)) * DMODEL + h * DHEAD;
#pragma unroll
    for (int i = 0; i < 4; i++) {
        *(float4*)(obase + (size_t)(ty * 4 + i) * DMODEL + tx * 4) =
            make_float4(oacc[i][0] * linv[i], oacc[i][1] * linv[i],
                        oacc[i][2] * linv[i], oacc[i][3] * linv[i]);
    }
}

// ---------------- orchestration -------------------------------------------
extern "C" void kernel_launch(void* const* d_in, const int* in_sizes, int n_in,
                              void* d_out, int out_size) {
    (void)in_sizes; (void)n_in; (void)out_size;
    const float* x_in    = (const float*)d_in[0];
    const int*   lengths = (const int*)d_in[1];
    const float* Wq = (const float*)d_in[2];
    const float* Wk = (const float*)d_in[3];
    const float* Wv = (const float*)d_in[4];
    const float* Wo = (const float*)d_in[5];
    const float* ln1g = (const float*)d_in[6];
    const float* ln1b = (const float*)d_in[7];
    const float* ln2g = (const float*)d_in[8];
    const float* ln2b = (const float*)d_in[9];
    const float* w1 = (const float*)d_in[10];
    const float* b1 = (const float*)d_in[11];
    const float* w2 = (const float*)d_in[12];
    const float* b2 = (const float*)d_in[13];

    float *px, *pq, *pk, *pv, *po;
    bf16 *phh, *phl, *pfh, *pfl, *pwh, *pwl;
    cudaGetSymbolAddress((void**)&px, g_x);
    cudaGetSymbolAddress((void**)&pq, g_q);
    cudaGetSymbolAddress((void**)&pk, g_k);
    cudaGetSymbolAddress((void**)&pv, g_v);
    cudaGetSymbolAddress((void**)&po, g_o);
    cudaGetSymbolAddress((void**)&phh, g_hh);
    cudaGetSymbolAddress((void**)&phl, g_hl);
    cudaGetSymbolAddress((void**)&pfh, g_fh);
    cudaGetSymbolAddress((void**)&pfl, g_fl);
    cudaGetSymbolAddress((void**)&pwh, g_wh);
    cudaGetSymbolAddress((void**)&pwl, g_wl);

    cudaFuncSetAttribute(k_attn, cudaFuncAttributeMaxDynamicSharedMemorySize, ATT_SMEM);
    cudaFuncSetAttribute(k_mm<false, false, false, false>,
                         cudaFuncAttributeMaxDynamicSharedMemorySize, GSMEM);
    cudaFuncSetAttribute(k_mm<false, false, true, false>,
                         cudaFuncAttributeMaxDynamicSharedMemorySize, GSMEM);
    cudaFuncSetAttribute(k_mm<true, true, false, true>,
                         cudaFuncAttributeMaxDynamicSharedMemorySize, GSMEM);
    cudaFuncSetAttribute(k_mm<true, false, true, false>,
                         cudaFuncAttributeMaxDynamicSharedMemorySize, GSMEM);

    // weight splits (once per call; graph replays them, they're cheap)
    k_split<<<WSZ_D / 1024, 256>>>(Wq, pwh + OFF_WQ, pwl + OFF_WQ, WSZ_D);
    k_split<<<WSZ_D / 1024, 256>>>(Wk, pwh + OFF_WK, pwl + OFF_WK, WSZ_D);
    k_split<<<WSZ_D / 1024, 256>>>(Wv, pwh + OFF_WV, pwl + OFF_WV, WSZ_D);
    k_split<<<WSZ_D / 1024, 256>>>(Wo, pwh + OFF_WO, pwl + OFF_WO, WSZ_D);
    k_split<<<WSZ_F / 1024, 256>>>(w1, pwh + OFF_W1, pwl + OFF_W1, WSZ_F);
    k_split<<<WSZ_F / 1024, 256>>>(w2, pwh + OFF_W2, pwl + OFF_W2, WSZ_F);

    k_pos<<<(BL * DMODEL) / 256, 256>>>(x_in, px);

    dim3 gD(DMODEL / GBN, BL / GBM);   // (4, 64)
    dim3 gF(DFF / GBN, BL / GBM);      // (16, 64)

    for (int layer = 0; layer < NLAYER; layer++) {
        const bf16* wqh = pwh + OFF_WQ + (size_t)layer * DMODEL * DMODEL;
        const bf16* wql = pwl + OFF_WQ + (size_t)layer * DMODEL * DMODEL;
        const bf16* wkh = pwh + OFF_WK + (size_t)layer * DMODEL * DMODEL;
        const bf16* wkl = pwl + OFF_WK + (size_t)layer * DMODEL * DMODEL;
        const bf16* wvh = pwh + OFF_WV + (size_t)layer * DMODEL * DMODEL;
        const bf16* wvl = pwl + OFF_WV + (size_t)layer * DMODEL * DMODEL;
        const bf16* woh = pwh + OFF_WO + (size_t)layer * DMODEL * DMODEL;
        const bf16* wol = pwl + OFF_WO + (size_t)layer * DMODEL * DMODEL;
        const bf16* w1h = pwh + OFF_W1 + (size_t)layer * DMODEL * DFF;
        const bf16* w1l = pwl + OFF_W1 + (size_t)layer * DMODEL * DFF;
        const bf16* w2h = pwh + OFF_W2 + (size_t)layer * DFF * DMODEL;
        const bf16* w2l = pwl + OFF_W2 + (size_t)layer * DFF * DMODEL;

        k_ln<<<BL, 128>>>(px, ln1g + (size_t)layer * DMODEL, ln1b + (size_t)layer * DMODEL,
                          phh, phl);
        k_mm<false, false, false, false><<<gD, 256, GSMEM>>>(
            phh, phl, wqh, wql, nullptr, nullptr, pq, nullptr, nullptr, BL, DMODEL, DMODEL);
        k_mm<false, false, false, false><<<gD, 256, GSMEM>>>(
            phh, phl, wkh, wkl, nullptr, nullptr, pk, nullptr, nullptr, BL, DMODEL, DMODEL);
        k_mm<false, false, false, false><<<gD, 256, GSMEM>>>(
            phh, phl, wvh, wvl, nullptr, nullptr, pv, nullptr, nullptr, BL, DMODEL, DMODEL);
        k_attn<<<dim3(SEQL / AT, NHEAD, BATCH), 256, ATT_SMEM>>>(pq, pk, pv, lengths, po);
        k_split<<<(BL * DMODEL) / 1024, 256>>>(po, phh, phl, BL * DMODEL);
        k_mm<false, false, true, false><<<gD, 256, GSMEM>>>(
            phh, phl, woh, wol, nullptr, px, px, nullptr, nullptr, BL, DMODEL, DMODEL);

        k_ln<<<BL, 128>>>(px, ln2g + (size_t)layer * DMODEL, ln2b + (size_t)layer * DMODEL,
                          phh, phl);
        k_mm<true, true, false, true><<<gF, 256, GSMEM>>>(
            phh, phl, w1h, w1l, b1 + (size_t)layer * DFF, nullptr,
            nullptr, pfh, pfl, BL, DFF, DMODEL);
        float* dst = (layer == NLAYER - 1) ? (float*)d_out : px;
        k_mm<true, false, true, false><<<gD, 256, GSMEM>>>(
            pfh, pfl, w2h, w2l, b2 + (size_t)layer * DMODEL, px,
            dst, nullptr, nullptr, BL, DMODEL, DFF);
    }
}

// round 3
// speedup vs baseline: 3.0831x; 1.4908x over previous
#include <cuda_runtime.h>
#include <cuda_bf16.h>
#include <math.h>
#include <stdint.h>

#define BATCH 8
#define SEQL 1024
#define DMODEL 512
#define NHEAD 8
#define DHEAD 64
#define DFF 2048
#define NLAYER 6
#define BL (BATCH * SEQL)   // 8192

typedef __nv_bfloat16 bf16;

// ---------------- scratch (device globals: no allocs allowed) -------------
__device__ __align__(128) float g_x[BL * DMODEL];
__device__ __align__(128) bf16  g_hh[BL * DMODEL];
__device__ __align__(128) bf16  g_hl[BL * DMODEL];
__device__ __align__(128) bf16  g_qh[BL * DMODEL];
__device__ __align__(128) bf16  g_ql[BL * DMODEL];
__device__ __align__(128) bf16  g_kh[BL * DMODEL];
__device__ __align__(128) bf16  g_kl[BL * DMODEL];
__device__ __align__(128) bf16  g_vh[BL * DMODEL];
__device__ __align__(128) bf16  g_vl[BL * DMODEL];
__device__ __align__(128) bf16  g_fh[BL * DFF];
__device__ __align__(128) bf16  g_fl[BL * DFF];
#define WSZ_D  (NLAYER * DMODEL * DMODEL)
#define WSZ_F  (NLAYER * DMODEL * DFF)
#define WTOT   (4 * WSZ_D + 2 * WSZ_F)
__device__ __align__(128) bf16  g_wh[WTOT];
__device__ __align__(128) bf16  g_wl[WTOT];
#define OFF_WQ 0
#define OFF_WK (1 * WSZ_D)
#define OFF_WV (2 * WSZ_D)
#define OFF_WO (3 * WSZ_D)
#define OFF_W1 (4 * WSZ_D)
#define OFF_W2 (4 * WSZ_D + WSZ_F)

// ---------------- helpers --------------------------------------------------
__device__ __forceinline__ void cp16(uint32_t s, const void* g) {
    asm volatile("cp.async.cg.shared.global [%0], [%1], 16;\n" :: "r"(s), "l"(g));
}
__device__ __forceinline__ void cp_commit() {
    asm volatile("cp.async.commit_group;\n" ::: "memory");
}
template <int N_>
__device__ __forceinline__ void cp_wait() {
    asm volatile("cp.async.wait_group %0;\n" :: "n"(N_) : "memory");
}
__device__ __forceinline__ void ldsm4(uint32_t* r, uint32_t addr) {
    asm volatile("ldmatrix.sync.aligned.m8n8.x4.shared.b16 {%0,%1,%2,%3}, [%4];"
                 : "=r"(r[0]), "=r"(r[1]), "=r"(r[2]), "=r"(r[3]) : "r"(addr));
}
__device__ __forceinline__ void ldsm4t(uint32_t* r, uint32_t addr) {
    asm volatile("ldmatrix.sync.aligned.m8n8.x4.trans.shared.b16 {%0,%1,%2,%3}, [%4];"
                 : "=r"(r[0]), "=r"(r[1]), "=r"(r[2]), "=r"(r[3]) : "r"(addr));
}
__device__ __forceinline__ void mma16816(float* c, const uint32_t* a, const uint32_t* b) {
    asm volatile(
        "mma.sync.aligned.m16n8k16.row.col.f32.bf16.bf16.f32 "
        "{%0,%1,%2,%3}, {%4,%5,%6,%7}, {%8,%9}, {%0,%1,%2,%3};"
        : "+f"(c[0]), "+f"(c[1]), "+f"(c[2]), "+f"(c[3])
        : "r"(a[0]), "r"(a[1]), "r"(a[2]), "r"(a[3]), "r"(b[0]), "r"(b[1]));
}
__device__ __forceinline__ uint32_t packbf(bf16 a, bf16 b) {
    return ((uint32_t)__bfloat16_as_ushort(b) << 16) | __bfloat16_as_ushort(a);
}
__device__ __forceinline__ void split2(float a, float b, uint32_t& hi, uint32_t& lo) {
    bf16 ha = __float2bfloat16_rn(a), hb = __float2bfloat16_rn(b);
    bf16 la = __float2bfloat16_rn(a - __bfloat162float(ha));
    bf16 lb = __float2bfloat16_rn(b - __bfloat162float(hb));
    hi = packbf(ha, hb);
    lo = packbf(la, lb);
}

// ---------------- positional embedding + add ------------------------------
__global__ void k_pos(const float* __restrict__ xin, float* __restrict__ xout) {
    int idx = blockIdx.x * 256 + threadIdx.x;
    if (idx >= BL * DMODEL) return;
    int d = idx % DMODEL;
    int l = (idx / DMODEL) % SEQL;
    int half = DMODEL / 2;
    int i = (d < half) ? d : d - half;
    float inv = powf(10000.0f, -2.0f * (float)i / (float)DMODEL);
    float ang = (float)l * inv;
    float pe = (d < half) ? sinf(ang) : cosf(ang);
    xout[idx] = xin[idx] + pe;
}

// ---------------- fp32 -> (hi,lo) bf16 split (weights) ---------------------
__global__ void k_split(const float* __restrict__ x, bf16* __restrict__ hi,
                        bf16* __restrict__ lo, int n) {
    int i = (blockIdx.x * 256 + threadIdx.x) * 4;
    if (i >= n) return;
    float4 v = *(const float4*)(x + i);
    uint32_t h0, l0, h1, l1;
    split2(v.x, v.y, h0, l0);
    split2(v.z, v.w, h1, l1);
    uint32_t* hp = (uint32_t*)(hi + i);
    uint32_t* lp = (uint32_t*)(lo + i);
    hp[0] = h0; hp[1] = h1;
    lp[0] = l0; lp[1] = l1;
}

// ---------------- layernorm -> split bf16 output --------------------------
__global__ void __launch_bounds__(128) k_ln(const float* __restrict__ x,
                                            const float* __restrict__ g,
                                            const float* __restrict__ b,
                                            bf16* __restrict__ ohi,
                                            bf16* __restrict__ olo) {
    int row = blockIdx.x;
    int tid = threadIdx.x;
    const float4* xr = (const float4*)(x + (size_t)row * DMODEL);
    float4 v = xr[tid];
    __shared__ float sh[4];

    float s = v.x + v.y + v.z + v.w;
    for (int o = 16; o; o >>= 1) s += __shfl_xor_sync(0xffffffffu, s, o);
    if ((tid & 31) == 0) sh[tid >> 5] = s;
    __syncthreads();
    float mean = (sh[0] + sh[1] + sh[2] + sh[3]) * (1.0f / DMODEL);
    __syncthreads();

    float dx0 = v.x - mean, dx1 = v.y - mean, dx2 = v.z - mean, dx3 = v.w - mean;
    float s2 = dx0 * dx0 + dx1 * dx1 + dx2 * dx2 + dx3 * dx3;
    for (int o = 16; o; o >>= 1) s2 += __shfl_xor_sync(0xffffffffu, s2, o);
    if ((tid & 31) == 0) sh[tid >> 5] = s2;
    __syncthreads();
    float var = (sh[0] + sh[1] + sh[2] + sh[3]) * (1.0f / DMODEL);
    float r = rsqrtf(var + 1e-3f);

    float4 gg = ((const float4*)g)[tid];
    float4 bb = ((const float4*)b)[tid];
    float o0 = dx0 * r * gg.x + bb.x;
    float o1 = dx1 * r * gg.y + bb.y;
    float o2 = dx2 * r * gg.z + bb.z;
    float o3 = dx3 * r * gg.w + bb.w;

    uint32_t h0, l0, h1, l1;
    split2(o0, o1, h0, l0);
    split2(o2, o3, h1, l1);
    size_t off = (size_t)row * DMODEL + tid * 4;
    uint32_t* hp = (uint32_t*)(ohi + off);
    uint32_t* lp = (uint32_t*)(olo + off);
    hp[0] = h0; hp[1] = h1;
    lp[0] = l0; lp[1] = l1;
}

// ---------------- bf16x3 tensor-core GEMM ---------------------------------
#define GBM 128
#define GBN 128
#define GBK 64
#define STAGE_ELEMS (2 * GBM * GBK + 2 * GBK * GBN)
#define SOFF_AH 0
#define SOFF_AL (GBM * GBK)
#define SOFF_BH (2 * GBM * GBK)
#define SOFF_BL (2 * GBM * GBK + GBK * GBN)
#define GSMEM (2 * STAGE_ELEMS * 2)

template <bool BIAS, bool RELU, bool RES, bool SPLIT>
__global__ void __launch_bounds__(256, 1) k_mm(
    const bf16* __restrict__ Ah, const bf16* __restrict__ Al,
    const bf16* __restrict__ Bh, const bf16* __restrict__ Bl,
    const float* __restrict__ bias, const float* __restrict__ res,
    float* __restrict__ Cf, bf16* __restrict__ Ch, bf16* __restrict__ Cl,
    int M, int N, int K) {
    extern __shared__ bf16 sm[];
    int tid = threadIdx.x;
    int lane = tid & 31, wid = tid >> 5;
    int wm = wid >> 2, wn = wid & 3;
    int m0 = blockIdx.y * GBM, n0 = blockIdx.x * GBN;
    uint32_t smbase = (uint32_t)__cvta_generic_to_shared(sm);

    float acc[4][4][4];
#pragma unroll
    for (int i = 0; i < 4; i++)
#pragma unroll
        for (int j = 0; j < 4; j++)
#pragma unroll
            for (int q = 0; q < 4; q++) acc[i][j][q] = 0.0f;

    int nk = K / GBK;

    auto load_stage = [&](int kt, int stg) {
        uint32_t sb = smbase + (uint32_t)stg * STAGE_ELEMS * 2;
#pragma unroll
        for (int p = 0; p < 4; p++) {
            int f = p * 256 + tid;
            int m = f >> 3, c = f & 7;
            uint32_t dst = (uint32_t)(m * GBK + ((c ^ (m & 7)) << 3));
            size_t src = (size_t)(m0 + m) * K + kt * GBK + (c << 3);
            cp16(sb + (SOFF_AH + dst) * 2, Ah + src);
            cp16(sb + (SOFF_AL + dst) * 2, Al + src);
        }
#pragma unroll
        for (int p = 0; p < 4; p++) {
            int f = p * 256 + tid;
            int k = f >> 4, c = f & 15;
            int cs = (c & 8) | ((c ^ (k & 7)) & 7);
            uint32_t dst = (uint32_t)(k * GBN + (cs << 3));
            size_t src = (size_t)(kt * GBK + k) * N + n0 + (c << 3);
            cp16(sb + (SOFF_BH + dst) * 2, Bh + src);
            cp16(sb + (SOFF_BL + dst) * 2, Bl + src);
        }
        cp_commit();
    };

    load_stage(0, 0);

    for (int kt = 0; kt < nk; kt++) {
        if (kt + 1 < nk) {
            load_stage(kt + 1, (kt + 1) & 1);
            cp_wait<1>();
        } else {
            cp_wait<0>();
        }
        __syncthreads();
        uint32_t sb = smbase + (uint32_t)(kt & 1) * STAGE_ELEMS * 2;

#pragma unroll
        for (int ks = 0; ks < GBK / 16; ks++) {
            uint32_t ah[4][4], al[4][4];
#pragma unroll
            for (int mt = 0; mt < 4; mt++) {
                int row = wm * 64 + mt * 16 + (lane & 15);
                int kc = ks * 2 + (lane >> 4);
                uint32_t off = (uint32_t)(row * GBK + ((kc ^ (row & 7)) << 3)) * 2;
                ldsm4(ah[mt], sb + SOFF_AH * 2 + off);
                ldsm4(al[mt], sb + SOFF_AL * 2 + off);
            }
            uint32_t bh[4][2], bl[4][2];
#pragma unroll
            for (int np = 0; np < 2; np++) {
                int krow = ks * 16 + (lane & 15);
                int nc = wn * 4 + np * 2 + (lane >> 4);
                int ncs = (nc & 8) | ((nc ^ (krow & 7)) & 7);
                uint32_t off = (uint32_t)(krow * GBN + (ncs << 3)) * 2;
                uint32_t r[4];
                ldsm4t(r, sb + SOFF_BH * 2 + off);
                bh[np * 2][0] = r[0]; bh[np * 2][1] = r[1];
                bh[np * 2 + 1][0] = r[2]; bh[np * 2 + 1][1] = r[3];
                ldsm4t(r, sb + SOFF_BL * 2 + off);
                bl[np * 2][0] = r[0]; bl[np * 2][1] = r[1];
                bl[np * 2 + 1][0] = r[2]; bl[np * 2 + 1][1] = r[3];
            }
#pragma unroll
            for (int mt = 0; mt < 4; mt++)
#pragma unroll
                for (int nt = 0; nt < 4; nt++) {
                    mma16816(acc[mt][nt], ah[mt], bh[nt]);
                    mma16816(acc[mt][nt], ah[mt], bl[nt]);
                    mma16816(acc[mt][nt], al[mt], bh[nt]);
                }
        }
        __syncthreads();
    }

#pragma unroll
    for (int mt = 0; mt < 4; mt++)
#pragma unroll
        for (int nt = 0; nt < 4; nt++) {
            int rbase = m0 + wm * 64 + mt * 16 + (lane >> 2);
            int cbase = n0 + wn * 32 + nt * 8 + (lane & 3) * 2;
#pragma unroll
            for (int half = 0; half < 2; half++) {
                int r = rbase + half * 8;
                float c0 = acc[mt][nt][half * 2 + 0];
                float c1 = acc[mt][nt][half * 2 + 1];
                size_t off = (size_t)r * N + cbase;
                if (BIAS) { c0 += bias[cbase]; c1 += bias[cbase + 1]; }
                if (RES)  { float2 rv = *(const float2*)(res + off); c0 += rv.x; c1 += rv.y; }
                if (RELU) { c0 = fmaxf(c0, 0.f); c1 = fmaxf(c1, 0.f); }
                if (SPLIT) {
                    uint32_t hi, lo;
                    split2(c0, c1, hi, lo);
                    *(uint32_t*)(Ch + off) = hi;
                    *(uint32_t*)(Cl + off) = lo;
                } else {
                    *(float2*)(Cf + off) = make_float2(c0, c1);
                }
            }
        }
}

// ---------------- tensor-core flash attention ------------------------------
// Block: 128 q-rows (8 warps x m16), K/V tile = 64 keys, DH=64.
// S = Q K^T via bf16x3, online softmax in regs, O = P V via bf16x3.
#define FBR 128
#define FBC 64
// smem layout in bf16 elems
#define FQ_H 0
#define FQ_L (FBR * 64)
#define FKV0 (2 * FBR * 64)
#define FKV_STRIDE (4 * FBC * 64)
#define FK_H 0
#define FK_L (FBC * 64)
#define FV_H (2 * FBC * 64)
#define FV_L (3 * FBC * 64)
#define FSMEM ((2 * FBR * 64 + 2 * FKV_STRIDE) * 2)   // 98304 bytes

__global__ void __launch_bounds__(256, 1) k_fattn(
    const bf16* __restrict__ Qh, const bf16* __restrict__ Ql,
    const bf16* __restrict__ Kh, const bf16* __restrict__ Kl,
    const bf16* __restrict__ Vh, const bf16* __restrict__ Vl,
    const int* __restrict__ lengths,
    bf16* __restrict__ Oh, bf16* __restrict__ Ol) {
    extern __shared__ bf16 sm[];
    uint32_t smb = (uint32_t)__cvta_generic_to_shared(sm);
    int b = blockIdx.z, h = blockIdx.y, qt = blockIdx.x;
    int len = lengths[b];
    int tid = threadIdx.x, lane = tid & 31, wid = tid >> 5;
    size_t qrow0 = (size_t)(b * SEQL + qt * FBR);
    size_t hoff = (size_t)h * DHEAD;

    auto load_kv = [&](int kt, int stg) {
        uint32_t sb = smb + (uint32_t)(FKV0 + stg * FKV_STRIDE) * 2;
        int kb = kt * FBC;
#pragma unroll
        for (int p = 0; p < 2; p++) {
            int f = p * 256 + tid;
            int r = f >> 3, c = f & 7;
            uint32_t d = (uint32_t)((r * 64 + ((c ^ (r & 7)) << 3)) * 2);
            size_t src = (size_t)(b * SEQL + kb + r) * DMODEL + hoff + (c << 3);
            cp16(sb + FK_H * 2 + d, Kh + src);
            cp16(sb + FK_L * 2 + d, Kl + src);
            cp16(sb + FV_H * 2 + d, Vh + src);
            cp16(sb + FV_L * 2 + d, Vl + src);
        }
        cp_commit();
    };

    load_kv(0, 0);

    // manual Q load -> smem (swizzled rows of 64)
#pragma unroll
    for (int p = 0; p < 4; p++) {
        int f = p * 256 + tid;
        int r = f >> 3, c = f & 7;
        uint32_t d = (uint32_t)(r * 64 + ((c ^ (r & 7)) << 3));
        size_t src = (qrow0 + r) * DMODEL + hoff + (c << 3);
        *(uint4*)(sm + FQ_H + d) = *(const uint4*)(Qh + src);
        *(uint4*)(sm + FQ_L + d) = *(const uint4*)(Ql + src);
    }
    __syncthreads();

    uint32_t qh[4][4], ql[4][4];
#pragma unroll
    for (int ks = 0; ks < 4; ks++) {
        int row = wid * 16 + (lane & 15);
        int kc = ks * 2 + (lane >> 4);
        uint32_t off = (uint32_t)(row * 64 + ((kc ^ (row & 7)) << 3)) * 2;
        ldsm4(qh[ks], smb + FQ_H * 2 + off);
        ldsm4(ql[ks], smb + FQ_L * 2 + off);
    }

    float o[8][4];
#pragma unroll
    for (int i = 0; i < 8; i++)
#pragma unroll
        for (int j = 0; j < 4; j++) o[i][j] = 0.0f;
    float m0 = -3.0e38f, m1 = -3.0e38f, l0 = 0.0f, l1 = 0.0f;

    int nkt = (len + FBC - 1) / FBC;
    for (int kt = 0; kt < nkt; kt++) {
        if (kt + 1 < nkt) { load_kv(kt + 1, (kt + 1) & 1); cp_wait<1>(); }
        else              { cp_wait<0>(); }
        __syncthreads();
        uint32_t sb = smb + (uint32_t)(FKV0 + (kt & 1) * FKV_STRIDE) * 2;

        // ---- S = Q K^T (scaled later) ----
        float s[8][4];
#pragma unroll
        for (int i = 0; i < 8; i++)
#pragma unroll
            for (int j = 0; j < 4; j++) s[i][j] = 0.0f;

#pragma unroll
        for (int ks = 0; ks < 4; ks++) {
#pragma unroll
            for (int kg = 0; kg < 4; kg++) {
                int key = kg * 16 + (lane & 15);
                int kc = ks * 2 + (lane >> 4);
                uint32_t off = (uint32_t)(key * 64 + ((kc ^ (key & 7)) << 3)) * 2;
                uint32_t rh[4], rl[4];
                ldsm4(rh, sb + FK_H * 2 + off);
                ldsm4(rl, sb + FK_L * 2 + off);
                uint32_t bh0[2] = {rh[0], rh[2]}, bh1[2] = {rh[1], rh[3]};
                uint32_t bl0[2] = {rl[0], rl[2]}, bl1[2] = {rl[1], rl[3]};
                mma16816(s[kg * 2], qh[ks], bh0);
                mma16816(s[kg * 2], qh[ks], bl0);
                mma16816(s[kg * 2], ql[ks], bh0);
                mma16816(s[kg * 2 + 1], qh[ks], bh1);
                mma16816(s[kg * 2 + 1], qh[ks], bl1);
                mma16816(s[kg * 2 + 1], ql[ks], bh1);
            }
        }

        // ---- online softmax (2 rows/thread) ----
        int colbase = kt * FBC + (lane & 3) * 2;
        float mx0 = -3.0e38f, mx1 = -3.0e38f;
#pragma unroll
        for (int nf = 0; nf < 8; nf++) {
            int c = colbase + nf * 8;
            float b0 = (c     >= len) ? -1e9f : 0.0f;
            float b1 = (c + 1 >= len) ? -1e9f : 0.0f;
            s[nf][0] = s[nf][0] * 0.125f + b0;
            s[nf][1] = s[nf][1] * 0.125f + b1;
            s[nf][2] = s[nf][2] * 0.125f + b0;
            s[nf][3] = s[nf][3] * 0.125f + b1;
            mx0 = fmaxf(mx0, fmaxf(s[nf][0], s[nf][1]));
            mx1 = fmaxf(mx1, fmaxf(s[nf][2], s[nf][3]));
        }
        mx0 = fmaxf(mx0, __shfl_xor_sync(0xffffffffu, mx0, 1));
        mx0 = fmaxf(mx0, __shfl_xor_sync(0xffffffffu, mx0, 2));
        mx1 = fmaxf(mx1, __shfl_xor_sync(0xffffffffu, mx1, 1));
        mx1 = fmaxf(mx1, __shfl_xor_sync(0xffffffffu, mx1, 2));
        float mn0 = fmaxf(m0, mx0), mn1 = fmaxf(m1, mx1);
        float a0 = __expf(m0 - mn0), a1 = __expf(m1 - mn1);
        float ls0 = 0.0f, ls1 = 0.0f;
#pragma unroll
        for (int nf = 0; nf < 8; nf++) {
            s[nf][0] = __expf(s[nf][0] - mn0);
            s[nf][1] = __expf(s[nf][1] - mn0);
            s[nf][2] = __expf(s[nf][2] - mn1);
            s[nf][3] = __expf(s[nf][3] - mn1);
            ls0 += s[nf][0] + s[nf][1];
            ls1 += s[nf][2] + s[nf][3];
        }
        ls0 += __shfl_xor_sync(0xffffffffu, ls0, 1);
        ls0 += __shfl_xor_sync(0xffffffffu, ls0, 2);
        ls1 += __shfl_xor_sync(0xffffffffu, ls1, 1);
        ls1 += __shfl_xor_sync(0xffffffffu, ls1, 2);
        l0 = l0 * a0 + ls0;
        l1 = l1 * a1 + ls1;
        m0 = mn0; m1 = mn1;
#pragma unroll
        for (int nf = 0; nf < 8; nf++) {
            o[nf][0] *= a0; o[nf][1] *= a0;
            o[nf][2] *= a1; o[nf][3] *= a1;
        }

        // ---- O += P V ----
#pragma unroll
        for (int kg = 0; kg < 4; kg++) {
            uint32_t ph[4], pl[4];
            split2(s[2 * kg][0], s[2 * kg][1], ph[0], pl[0]);
            split2(s[2 * kg][2], s[2 * kg][3], ph[1], pl[1]);
            split2(s[2 * kg + 1][0], s[2 * kg + 1][1], ph[2], pl[2]);
            split2(s[2 * kg + 1][2], s[2 * kg + 1][3], ph[3], pl[3]);
#pragma unroll
            for (int np = 0; np < 4; np++) {
                int krow = kg * 16 + (lane & 15);
                int nc = np * 2 + (lane >> 4);
                uint32_t off = (uint32_t)(krow * 64 + ((nc ^ (krow & 7)) << 3)) * 2;
                uint32_t rh[4], rl[4];
                ldsm4t(rh, sb + FV_H * 2 + off);
                ldsm4t(rl, sb + FV_L * 2 + off);
                uint32_t vh0[2] = {rh[0], rh[1]}, vh1[2] = {rh[2], rh[3]};
                uint32_t vl0[2] = {rl[0], rl[1]}, vl1[2] = {rl[2], rl[3]};
                mma16816(o[np * 2], ph, vh0);
                mma16816(o[np * 2], ph, vl0);
                mma16816(o[np * 2], pl, vh0);
                mma16816(o[np * 2 + 1], ph, vh1);
                mma16816(o[np * 2 + 1], ph, vl1);
                mma16816(o[np * 2 + 1], pl, vh1);
            }
        }
        __syncthreads();   // protect smem stage reuse before next prefetch
    }

    // ---- finalize & write split bf16 ----
    float li0 = 1.0f / l0, li1 = 1.0f / l1;
    int r0 = wid * 16 + (lane >> 2);
    size_t row0 = (qrow0 + r0) * DMODEL + hoff + (lane & 3) * 2;
    size_t row1 = (qrow0 + r0 + 8) * DMODEL + hoff + (lane & 3) * 2;
#pragma unroll
    for (int nf = 0; nf < 8; nf++) {
        uint32_t hi, lo;
        split2(o[nf][0] * li0, o[nf][1] * li0, hi, lo);
        *(uint32_t*)(Oh + row0 + nf * 8) = hi;
        *(uint32_t*)(Ol + row0 + nf * 8) = lo;
        split2(o[nf][2] * li1, o[nf][3] * li1, hi, lo);
        *(uint32_t*)(Oh + row1 + nf * 8) = hi;
        *(uint32_t*)(Ol + row1 + nf * 8) = lo;
    }
}

// ---------------- orchestration -------------------------------------------
extern "C" void kernel_launch(void* const* d_in, const int* in_sizes, int n_in,
                              void* d_out, int out_size) {
    (void)in_sizes; (void)n_in; (void)out_size;
    const float* x_in    = (const float*)d_in[0];
    const int*   lengths = (const int*)d_in[1];
    const float* Wq = (const float*)d_in[2];
    const float* Wk = (const float*)d_in[3];
    const float* Wv = (const float*)d_in[4];
    const float* Wo = (const float*)d_in[5];
    const float* ln1g = (const float*)d_in[6];
    const float* ln1b = (const float*)d_in[7];
    const float* ln2g = (const float*)d_in[8];
    const float* ln2b = (const float*)d_in[9];
    const float* w1 = (const float*)d_in[10];
    const float* b1 = (const float*)d_in[11];
    const float* w2 = (const float*)d_in[12];
    const float* b2 = (const float*)d_in[13];

    float* px;
    bf16 *phh, *phl, *pqh, *pql, *pkh, *pkl, *pvh, *pvl, *pfh, *pfl, *pwh, *pwl;
    cudaGetSymbolAddress((void**)&px, g_x);
    cudaGetSymbolAddress((void**)&phh, g_hh);
    cudaGetSymbolAddress((void**)&phl, g_hl);
    cudaGetSymbolAddress((void**)&pqh, g_qh);
    cudaGetSymbolAddress((void**)&pql, g_ql);
    cudaGetSymbolAddress((void**)&pkh, g_kh);
    cudaGetSymbolAddress((void**)&pkl, g_kl);
    cudaGetSymbolAddress((void**)&pvh, g_vh);
    cudaGetSymbolAddress((void**)&pvl, g_vl);
    cudaGetSymbolAddress((void**)&pfh, g_fh);
    cudaGetSymbolAddress((void**)&pfl, g_fl);
    cudaGetSymbolAddress((void**)&pwh, g_wh);
    cudaGetSymbolAddress((void**)&pwl, g_wl);

    cudaFuncSetAttribute(k_fattn, cudaFuncAttributeMaxDynamicSharedMemorySize, FSMEM);
    cudaFuncSetAttribute(k_mm<false, false, false, true>,
                         cudaFuncAttributeMaxDynamicSharedMemorySize, GSMEM);
    cudaFuncSetAttribute(k_mm<false, false, true, false>,
                         cudaFuncAttributeMaxDynamicSharedMemorySize, GSMEM);
    cudaFuncSetAttribute(k_mm<true, true, false, true>,
                         cudaFuncAttributeMaxDynamicSharedMemorySize, GSMEM);
    cudaFuncSetAttribute(k_mm<true, false, true, false>,
                         cudaFuncAttributeMaxDynamicSharedMemorySize, GSMEM);

    k_split<<<WSZ_D / 1024, 256>>>(Wq, pwh + OFF_WQ, pwl + OFF_WQ, WSZ_D);
    k_split<<<WSZ_D / 1024, 256>>>(Wk, pwh + OFF_WK, pwl + OFF_WK, WSZ_D);
    k_split<<<WSZ_D / 1024, 256>>>(Wv, pwh + OFF_WV, pwl + OFF_WV, WSZ_D);
    k_split<<<WSZ_D / 1024, 256>>>(Wo, pwh + OFF_WO, pwl + OFF_WO, WSZ_D);
    k_split<<<WSZ_F / 1024, 256>>>(w1, pwh + OFF_W1, pwl + OFF_W1, WSZ_F);
    k_split<<<WSZ_F / 1024, 256>>>(w2, pwh + OFF_W2, pwl + OFF_W2, WSZ_F);

    k_pos<<<(BL * DMODEL) / 256, 256>>>(x_in, px);

    dim3 gD(DMODEL / GBN, BL / GBM);
    dim3 gF(DFF / GBN, BL / GBM);
    dim3 gA(SEQL / FBR, NHEAD, BATCH);

    for (int layer = 0; layer < NLAYER; layer++) {
        const bf16* wqh = pwh + OFF_WQ + (size_t)layer * DMODEL * DMODEL;
        const bf16* wql = pwl + OFF_WQ + (size_t)layer * DMODEL * DMODEL;
        const bf16* wkh = pwh + OFF_WK + (size_t)layer * DMODEL * DMODEL;
        const bf16* wkl = pwl + OFF_WK + (size_t)layer * DMODEL * DMODEL;
        const bf16* wvh = pwh + OFF_WV + (size_t)layer * DMODEL * DMODEL;
        const bf16* wvl = pwl + OFF_WV + (size_t)layer * DMODEL * DMODEL;
        const bf16* woh = pwh + OFF_WO + (size_t)layer * DMODEL * DMODEL;
        const bf16* wol = pwl + OFF_WO + (size_t)layer * DMODEL * DMODEL;
        const bf16* w1h = pwh + OFF_W1 + (size_t)layer * DMODEL * DFF;
        const bf16* w1l = pwl + OFF_W1 + (size_t)layer * DMODEL * DFF;
        const bf16* w2h = pwh + OFF_W2 + (size_t)layer * DFF * DMODEL;
        const bf16* w2l = pwl + OFF_W2 + (size_t)layer * DFF * DMODEL;

        k_ln<<<BL, 128>>>(px, ln1g + (size_t)layer * DMODEL, ln1b + (size_t)layer * DMODEL,
                          phh, phl);
        k_mm<false, false, false, true><<<gD, 256, GSMEM>>>(
            phh, phl, wqh, wql, nullptr, nullptr, nullptr, pqh, pql, BL, DMODEL, DMODEL);
        k_mm<false, false, false, true><<<gD, 256, GSMEM>>>(
            phh, phl, wkh, wkl, nullptr, nullptr, nullptr, pkh, pkl, BL, DMODEL, DMODEL);
        k_mm<false, false, false, true><<<gD, 256, GSMEM>>>(
            phh, phl, wvh, wvl, nullptr, nullptr, nullptr, pvh, pvl, BL, DMODEL, DMODEL);
        k_fattn<<<gA, 256, FSMEM>>>(pqh, pql, pkh, pkl, pvh, pvl, lengths, phh, phl);
        k_mm<false, false, true, false><<<gD, 256, GSMEM>>>(
            phh, phl, woh, wol, nullptr, px, px, nullptr, nullptr, BL, DMODEL, DMODEL);

        k_ln<<<BL, 128>>>(px, ln2g + (size_t)layer * DMODEL, ln2b + (size_t)layer * DMODEL,
                          phh, phl);
        k_mm<true, true, false, true><<<gF, 256, GSMEM>>>(
            phh, phl, w1h, w1l, b1 + (size_t)layer * DFF, nullptr,
            nullptr, pfh, pfl, BL, DFF, DMODEL);
        float* dst = (layer == NLAYER - 1) ? (float*)d_out : px;
        k_mm<true, false, true, false><<<gD, 256, GSMEM>>>(
            pfh, pfl, w2h, w2l, b2 + (size_t)layer * DMODEL, px,
            dst, nullptr, nullptr, BL, DMODEL, DFF);
    }
}

// round 5
// speedup vs baseline: 3.1444x; 1.0199x over previous
#include <cuda_runtime.h>
#include <cuda_bf16.h>
#include <math.h>
#include <stdint.h>

#define BATCH 8
#define SEQL 1024
#define DMODEL 512
#define NHEAD 8
#define DHEAD 64
#define DFF 2048
#define NLAYER 6
#define BL (BATCH * SEQL)   // 8192
#define QKVS 1536           // fused QKV row stride

typedef __nv_bfloat16 bf16;

// ---------------- scratch (device globals: no allocs allowed) -------------
__device__ __align__(128) float g_x[BL * DMODEL];
__device__ __align__(128) bf16  g_hh[BL * DMODEL];
__device__ __align__(128) bf16  g_hl[BL * DMODEL];
__device__ __align__(128) bf16  g_qkvh[BL * QKVS];
__device__ __align__(128) bf16  g_qkvl[BL * QKVS];
__device__ __align__(128) bf16  g_fh[BL * DFF];
__device__ __align__(128) bf16  g_fl[BL * DFF];

// weight regions (all [K][N] row-major, bf16 hi/lo split)
#define SZ_QKV (NLAYER * DMODEL * QKVS)        // 4718592
#define SZ_WO  (NLAYER * DMODEL * DMODEL)      // 1572864
#define SZ_W1  (NLAYER * DMODEL * DFF)         // 6291456
#define SZ_W2  (NLAYER * DFF * DMODEL)         // 6291456
#define OFF_QKV 0
#define OFF_WO  (OFF_QKV + SZ_QKV)
#define OFF_W1  (OFF_WO + SZ_WO)
#define OFF_W2  (OFF_W1 + SZ_W1)
#define WTOT    (OFF_W2 + SZ_W2)
__device__ __align__(128) bf16  g_wh[WTOT];
__device__ __align__(128) bf16  g_wl[WTOT];

// ---------------- helpers --------------------------------------------------
__device__ __forceinline__ void cp16(uint32_t s, const void* g) {
    asm volatile("cp.async.cg.shared.global [%0], [%1], 16;\n" :: "r"(s), "l"(g));
}
__device__ __forceinline__ void cp_commit() {
    asm volatile("cp.async.commit_group;\n" ::: "memory");
}
template <int N_>
__device__ __forceinline__ void cp_wait() {
    asm volatile("cp.async.wait_group %0;\n" :: "n"(N_) : "memory");
}
__device__ __forceinline__ void ldsm4(uint32_t* r, uint32_t addr) {
    asm volatile("ldmatrix.sync.aligned.m8n8.x4.shared.b16 {%0,%1,%2,%3}, [%4];"
                 : "=r"(r[0]), "=r"(r[1]), "=r"(r[2]), "=r"(r[3]) : "r"(addr));
}
__device__ __forceinline__ void ldsm4t(uint32_t* r, uint32_t addr) {
    asm volatile("ldmatrix.sync.aligned.m8n8.x4.trans.shared.b16 {%0,%1,%2,%3}, [%4];"
                 : "=r"(r[0]), "=r"(r[1]), "=r"(r[2]), "=r"(r[3]) : "r"(addr));
}
__device__ __forceinline__ void mma16816(float* c, const uint32_t* a, const uint32_t* b) {
    asm volatile(
        "mma.sync.aligned.m16n8k16.row.col.f32.bf16.bf16.f32 "
        "{%0,%1,%2,%3}, {%4,%5,%6,%7}, {%8,%9}, {%0,%1,%2,%3};"
        : "+f"(c[0]), "+f"(c[1]), "+f"(c[2]), "+f"(c[3])
        : "r"(a[0]), "r"(a[1]), "r"(a[2]), "r"(a[3]), "r"(b[0]), "r"(b[1]));
}
__device__ __forceinline__ uint32_t packbf(bf16 a, bf16 b) {
    return ((uint32_t)__bfloat16_as_ushort(b) << 16) | __bfloat16_as_ushort(a);
}
__device__ __forceinline__ void split2(float a, float b, uint32_t& hi, uint32_t& lo) {
    bf16 ha = __float2bfloat16_rn(a), hb = __float2bfloat16_rn(b);
    bf16 la = __float2bfloat16_rn(a - __bfloat162float(ha));
    bf16 lb = __float2bfloat16_rn(b - __bfloat162float(hb));
    hi = packbf(ha, hb);
    lo = packbf(la, lb);
}

// ---------------- positional embedding + add ------------------------------
__global__ void k_pos(const float* __restrict__ xin, float* __restrict__ xout) {
    int idx = blockIdx.x * 256 + threadIdx.x;
    if (idx >= BL * DMODEL) return;
    int d = idx % DMODEL;
    int l = (idx / DMODEL) % SEQL;
    int half = DMODEL / 2;
    int i = (d < half) ? d : d - half;
    float inv = powf(10000.0f, -2.0f * (float)i / (float)DMODEL);
    float ang = (float)l * inv;
    float pe = (d < half) ? sinf(ang) : cosf(ang);
    xout[idx] = xin[idx] + pe;
}

// ---------------- ONE combined weight split kernel -------------------------
// Builds: QKV concat [l][512][1536], WO [l][512][512], W1 [l][512][2048],
//         W2 [l][2048][512] as (hi,lo) bf16 splits.
__global__ void __launch_bounds__(256) k_wsplit(
    const float* __restrict__ Wq, const float* __restrict__ Wk,
    const float* __restrict__ Wv, const float* __restrict__ Wo,
    const float* __restrict__ w1, const float* __restrict__ w2,
    bf16* __restrict__ dh, bf16* __restrict__ dl) {
    uint32_t idx = (blockIdx.x * 256 + threadIdx.x) * 4;
    if (idx >= WTOT) return;
    const float* src;
    if (idx < OFF_WO) {
        uint32_t rel = idx;                       // QKV region
        uint32_t l = rel / (DMODEL * QKVS);
        uint32_t r2 = rel - l * (DMODEL * QKVS);
        uint32_t k = r2 / QKVS;
        uint32_t j = r2 - k * QKVS;
        uint32_t sel = j >> 9;                    // 0,1,2
        uint32_t jj = j & 511;
        const float* W = (sel == 0) ? Wq : (sel == 1) ? Wk : Wv;
        src = W + (size_t)l * DMODEL * DMODEL + (size_t)k * DMODEL + jj;
    } else if (idx < OFF_W1) {
        src = Wo + (idx - OFF_WO);
    } else if (idx < OFF_W2) {
        src = w1 + (idx - OFF_W1);
    } else {
        src = w2 + (idx - OFF_W2);
    }
    float4 v = *(const float4*)src;
    uint32_t h0, l0, h1, l1;
    split2(v.x, v.y, h0, l0);
    split2(v.z, v.w, h1, l1);
    uint32_t* hp = (uint32_t*)(dh + idx);
    uint32_t* lp = (uint32_t*)(dl + idx);
    hp[0] = h0; hp[1] = h1;
    lp[0] = l0; lp[1] = l1;
}

// ---------------- layernorm -> split bf16 output --------------------------
__global__ void __launch_bounds__(128) k_ln(const float* __restrict__ x,
                                            const float* __restrict__ g,
                                            const float* __restrict__ b,
                                            bf16* __restrict__ ohi,
                                            bf16* __restrict__ olo) {
    int row = blockIdx.x;
    int tid = threadIdx.x;
    const float4* xr = (const float4*)(x + (size_t)row * DMODEL);
    float4 v = xr[tid];
    __shared__ float sh[4];

    float s = v.x + v.y + v.z + v.w;
    for (int o = 16; o; o >>= 1) s += __shfl_xor_sync(0xffffffffu, s, o);
    if ((tid & 31) == 0) sh[tid >> 5] = s;
    __syncthreads();
    float mean = (sh[0] + sh[1] + sh[2] + sh[3]) * (1.0f / DMODEL);
    __syncthreads();

    float dx0 = v.x - mean, dx1 = v.y - mean, dx2 = v.z - mean, dx3 = v.w - mean;
    float s2 = dx0 * dx0 + dx1 * dx1 + dx2 * dx2 + dx3 * dx3;
    for (int o = 16; o; o >>= 1) s2 += __shfl_xor_sync(0xffffffffu, s2, o);
    if ((tid & 31) == 0) sh[tid >> 5] = s2;
    __syncthreads();
    float var = (sh[0] + sh[1] + sh[2] + sh[3]) * (1.0f / DMODEL);
    float r = rsqrtf(var + 1e-3f);

    float4 gg = ((const float4*)g)[tid];
    float4 bb = ((const float4*)b)[tid];
    float o0 = dx0 * r * gg.x + bb.x;
    float o1 = dx1 * r * gg.y + bb.y;
    float o2 = dx2 * r * gg.z + bb.z;
    float o3 = dx3 * r * gg.w + bb.w;

    uint32_t h0, l0, h1, l1;
    split2(o0, o1, h0, l0);
    split2(o2, o3, h1, l1);
    size_t off = (size_t)row * DMODEL + tid * 4;
    uint32_t* hp = (uint32_t*)(ohi + off);
    uint32_t* lp = (uint32_t*)(olo + off);
    hp[0] = h0; hp[1] = h1;
    lp[0] = l0; lp[1] = l1;
}

// ---------------- bf16x3 HMMA GEMM, 3-stage cp.async ring ------------------
// C[M,N] = A[M,K] @ B[K,N] via Ahi*Bhi + Ahi*Blo + Alo*Bhi (fp32 acc)
#define GBM 128
#define GBN 128
#define GBK 64
#define NSTAGE 3
#define STAGE_ELEMS (2 * GBM * GBK + 2 * GBK * GBN)   // 32768 bf16 = 64 KB
#define STAGE_BYTES (STAGE_ELEMS * 2)
#define SOFF_AH 0
#define SOFF_AL (GBM * GBK)
#define SOFF_BH (2 * GBM * GBK)
#define SOFF_BL (2 * GBM * GBK + GBK * GBN)
#define GSMEM (NSTAGE * STAGE_BYTES)                  // 196608 bytes

template <bool BIAS, bool RELU, bool RES, bool SPLIT>
__global__ void __launch_bounds__(256, 1) k_mm(
    const bf16* __restrict__ Ah, const bf16* __restrict__ Al,
    const bf16* __restrict__ Bh, const bf16* __restrict__ Bl,
    const float* __restrict__ bias, const float* __restrict__ res,
    float* __restrict__ Cf, bf16* __restrict__ Ch, bf16* __restrict__ Cl,
    int M, int N, int K) {
    extern __shared__ bf16 sm[];
    int tid = threadIdx.x;
    int lane = tid & 31, wid = tid >> 5;
    int wm = wid >> 2, wn = wid & 3;
    int m0 = blockIdx.y * GBM, n0 = blockIdx.x * GBN;
    uint32_t smbase = (uint32_t)__cvta_generic_to_shared(sm);

    float acc[4][4][4];
#pragma unroll
    for (int i = 0; i < 4; i++)
#pragma unroll
        for (int j = 0; j < 4; j++)
#pragma unroll
            for (int q = 0; q < 4; q++) acc[i][j][q] = 0.0f;

    int nk = K / GBK;

    auto load_stage = [&](int kt, int buf) {
        uint32_t sb = smbase + (uint32_t)buf * STAGE_BYTES;
#pragma unroll
        for (int p = 0; p < 4; p++) {
            int f = p * 256 + tid;
            int m = f >> 3, c = f & 7;
            uint32_t dst = (uint32_t)(m * GBK + ((c ^ (m & 7)) << 3));
            size_t src = (size_t)(m0 + m) * K + kt * GBK + (c << 3);
            cp16(sb + (SOFF_AH + dst) * 2, Ah + src);
            cp16(sb + (SOFF_AL + dst) * 2, Al + src);
        }
#pragma unroll
        for (int p = 0; p < 4; p++) {
            int f = p * 256 + tid;
            int k = f >> 4, c = f & 15;
            int cs = (c & 8) | ((c ^ (k & 7)) & 7);
            uint32_t dst = (uint32_t)(k * GBN + (cs << 3));
            size_t src = (size_t)(kt * GBK + k) * N + n0 + (c << 3);
            cp16(sb + (SOFF_BH + dst) * 2, Bh + src);
            cp16(sb + (SOFF_BL + dst) * 2, Bl + src);
        }
    };

    // prologue: stages 0,1 in flight
    load_stage(0, 0); cp_commit();
    if (nk > 1) load_stage(1, 1);
    cp_commit();

    int bufc = 0, bufl = 2;
    for (int kt = 0; kt < nk; kt++) {
        cp_wait<1>();           // stage kt complete
        __syncthreads();        // all warps finished compute kt-1
        if (kt + 2 < nk) load_stage(kt + 2, bufl);
        cp_commit();

        uint32_t sb = smbase + (uint32_t)bufc * STAGE_BYTES;
#pragma unroll
        for (int ks = 0; ks < GBK / 16; ks++) {
            uint32_t ah[4][4], al[4][4];
#pragma unroll
            for (int mt = 0; mt < 4; mt++) {
                int row = wm * 64 + mt * 16 + (lane & 15);
                int kc = ks * 2 + (lane >> 4);
                uint32_t off = (uint32_t)(row * GBK + ((kc ^ (row & 7)) << 3)) * 2;
                ldsm4(ah[mt], sb + SOFF_AH * 2 + off);
                ldsm4(al[mt], sb + SOFF_AL * 2 + off);
            }
            uint32_t bh[4][2], bl[4][2];
#pragma unroll
            for (int np = 0; np < 2; np++) {
                int krow = ks * 16 + (lane & 15);
                int nc = wn * 4 + np * 2 + (lane >> 4);
                int ncs = (nc & 8) | ((nc ^ (krow & 7)) & 7);
                uint32_t off = (uint32_t)(krow * GBN + (ncs << 3)) * 2;
                uint32_t r[4];
                ldsm4t(r, sb + SOFF_BH * 2 + off);
                bh[np * 2][0] = r[0]; bh[np * 2][1] = r[1];
                bh[np * 2 + 1][0] = r[2]; bh[np * 2 + 1][1] = r[3];
                ldsm4t(r, sb + SOFF_BL * 2 + off);
                bl[np * 2][0] = r[0]; bl[np * 2][1] = r[1];
                bl[np * 2 + 1][0] = r[2]; bl[np * 2 + 1][1] = r[3];
            }
#pragma unroll
            for (int mt = 0; mt < 4; mt++)
#pragma unroll
                for (int nt = 0; nt < 4; nt++) {
                    mma16816(acc[mt][nt], ah[mt], bh[nt]);
                    mma16816(acc[mt][nt], ah[mt], bl[nt]);
                    mma16816(acc[mt][nt], al[mt], bh[nt]);
                }
        }
        bufc = (bufc == NSTAGE - 1) ? 0 : bufc + 1;
        bufl = (bufl == NSTAGE - 1) ? 0 : bufl + 1;
    }

#pragma unroll
    for (int mt = 0; mt < 4; mt++)
#pragma unroll
        for (int nt = 0; nt < 4; nt++) {
            int rbase = m0 + wm * 64 + mt * 16 + (lane >> 2);
            int cbase = n0 + wn * 32 + nt * 8 + (lane & 3) * 2;
#pragma unroll
            for (int half = 0; half < 2; half++) {
                int r = rbase + half * 8;
                float c0 = acc[mt][nt][half * 2 + 0];
                float c1 = acc[mt][nt][half * 2 + 1];
                size_t off = (size_t)r * N + cbase;
                if (BIAS) { c0 += bias[cbase]; c1 += bias[cbase + 1]; }
                if (RES)  { float2 rv = *(const float2*)(res + off); c0 += rv.x; c1 += rv.y; }
                if (RELU) { c0 = fmaxf(c0, 0.f); c1 = fmaxf(c1, 0.f); }
                if (SPLIT) {
                    uint32_t hi, lo;
                    split2(c0, c1, hi, lo);
                    *(uint32_t*)(Ch + off) = hi;
                    *(uint32_t*)(Cl + off) = lo;
                } else {
                    *(float2*)(Cf + off) = make_float2(c0, c1);
                }
            }
        }
}

// ---------------- tensor-core flash attention (reads fused QKV buffer) -----
#define FBR 128
#define FBC 64
#define FQ_H 0
#define FQ_L (FBR * 64)
#define FKV0 (2 * FBR * 64)
#define FKV_STRIDE (4 * FBC * 64)
#define FK_H 0
#define FK_L (FBC * 64)
#define FV_H (2 * FBC * 64)
#define FV_L (3 * FBC * 64)
#define FSMEM ((2 * FBR * 64 + 2 * FKV_STRIDE) * 2)

__global__ void __launch_bounds__(256, 1) k_fattn(
    const bf16* __restrict__ QKVh, const bf16* __restrict__ QKVl,
    const int* __restrict__ lengths,
    bf16* __restrict__ Oh, bf16* __restrict__ Ol) {
    extern __shared__ bf16 sm[];
    uint32_t smb = (uint32_t)__cvta_generic_to_shared(sm);
    int b = blockIdx.z, h = blockIdx.y, qt = blockIdx.x;
    int len = lengths[b];
    int tid = threadIdx.x, lane = tid & 31, wid = tid >> 5;
    size_t qrow0 = (size_t)(b * SEQL + qt * FBR);
    size_t hoff = (size_t)h * DHEAD;

    auto load_kv = [&](int kt, int stg) {
        uint32_t sb = smb + (uint32_t)(FKV0 + stg * FKV_STRIDE) * 2;
        int kb = kt * FBC;
#pragma unroll
        for (int p = 0; p < 2; p++) {
            int f = p * 256 + tid;
            int r = f >> 3, c = f & 7;
            uint32_t d = (uint32_t)((r * 64 + ((c ^ (r & 7)) << 3)) * 2);
            size_t src = (size_t)(b * SEQL + kb + r) * QKVS + hoff + (c << 3);
            cp16(sb + FK_H * 2 + d, QKVh + src + 512);
            cp16(sb + FK_L * 2 + d, QKVl + src + 512);
            cp16(sb + FV_H * 2 + d, QKVh + src + 1024);
            cp16(sb + FV_L * 2 + d, QKVl + src + 1024);
        }
        cp_commit();
    };

    load_kv(0, 0);

#pragma unroll
    for (int p = 0; p < 4; p++) {
        int f = p * 256 + tid;
        int r = f >> 3, c = f & 7;
        uint32_t d = (uint32_t)(r * 64 + ((c ^ (r & 7)) << 3));
        size_t src = (qrow0 + r) * QKVS + hoff + (c << 3);
        *(uint4*)(sm + FQ_H + d) = *(const uint4*)(QKVh + src);
        *(uint4*)(sm + FQ_L + d) = *(const uint4*)(QKVl + src);
    }
    __syncthreads();

    uint32_t qh[4][4], ql[4][4];
#pragma unroll
    for (int ks = 0; ks < 4; ks++) {
        int row = wid * 16 + (lane & 15);
        int kc = ks * 2 + (lane >> 4);
        uint32_t off = (uint32_t)(row * 64 + ((kc ^ (row & 7)) << 3)) * 2;
        ldsm4(qh[ks], smb + FQ_H * 2 + off);
        ldsm4(ql[ks], smb + FQ_L * 2 + off);
    }

    float o[8][4];
#pragma unroll
    for (int i = 0; i < 8; i++)
#pragma unroll
        for (int j = 0; j < 4; j++) o[i][j] = 0.0f;
    float m0 = -3.0e38f, m1 = -3.0e38f, l0 = 0.0f, l1 = 0.0f;

    int nkt = (len + FBC - 1) / FBC;
    for (int kt = 0; kt < nkt; kt++) {
        if (kt + 1 < nkt) { load_kv(kt + 1, (kt + 1) & 1); cp_wait<1>(); }
        else              { cp_wait<0>(); }
        __syncthreads();
        uint32_t sb = smb + (uint32_t)(FKV0 + (kt & 1) * FKV_STRIDE) * 2;

        float s[8][4];
#pragma unroll
        for (int i = 0; i < 8; i++)
#pragma unroll
            for (int j = 0; j < 4; j++) s[i][j] = 0.0f;

#pragma unroll
        for (int ks = 0; ks < 4; ks++) {
#pragma unroll
            for (int kg = 0; kg < 4; kg++) {
                int key = kg * 16 + (lane & 15);
                int kc = ks * 2 + (lane >> 4);
                uint32_t off = (uint32_t)(key * 64 + ((kc ^ (key & 7)) << 3)) * 2;
                uint32_t rh[4], rl[4];
                ldsm4(rh, sb + FK_H * 2 + off);
                ldsm4(rl, sb + FK_L * 2 + off);
                uint32_t bh0[2] = {rh[0], rh[2]}, bh1[2] = {rh[1], rh[3]};
                uint32_t bl0[2] = {rl[0], rl[2]}, bl1[2] = {rl[1], rl[3]};
                mma16816(s[kg * 2], qh[ks], bh0);
                mma16816(s[kg * 2], qh[ks], bl0);
                mma16816(s[kg * 2], ql[ks], bh0);
                mma16816(s[kg * 2 + 1], qh[ks], bh1);
                mma16816(s[kg * 2 + 1], qh[ks], bl1);
                mma16816(s[kg * 2 + 1], ql[ks], bh1);
            }
        }

        int colbase = kt * FBC + (lane & 3) * 2;
        float mx0 = -3.0e38f, mx1 = -3.0e38f;
#pragma unroll
        for (int nf = 0; nf < 8; nf++) {
            int c = colbase + nf * 8;
            float b0 = (c     >= len) ? -1e9f : 0.0f;
            float b1 = (c + 1 >= len) ? -1e9f : 0.0f;
            s[nf][0] = s[nf][0] * 0.125f + b0;
            s[nf][1] = s[nf][1] * 0.125f + b1;
            s[nf][2] = s[nf][2] * 0.125f + b0;
            s[nf][3] = s[nf][3] * 0.125f + b1;
            mx0 = fmaxf(mx0, fmaxf(s[nf][0], s[nf][1]));
            mx1 = fmaxf(mx1, fmaxf(s[nf][2], s[nf][3]));
        }
        mx0 = fmaxf(mx0, __shfl_xor_sync(0xffffffffu, mx0, 1));
        mx0 = fmaxf(mx0, __shfl_xor_sync(0xffffffffu, mx0, 2));
        mx1 = fmaxf(mx1, __shfl_xor_sync(0xffffffffu, mx1, 1));
        mx1 = fmaxf(mx1, __shfl_xor_sync(0xffffffffu, mx1, 2));
        float mn0 = fmaxf(m0, mx0), mn1 = fmaxf(m1, mx1);
        float a0 = __expf(m0 - mn0), a1 = __expf(m1 - mn1);
        float ls0 = 0.0f, ls1 = 0.0f;
#pragma unroll
        for (int nf = 0; nf < 8; nf++) {
            s[nf][0] = __expf(s[nf][0] - mn0);
            s[nf][1] = __expf(s[nf][1] - mn0);
            s[nf][2] = __expf(s[nf][2] - mn1);
            s[nf][3] = __expf(s[nf][3] - mn1);
            ls0 += s[nf][0] + s[nf][1];
            ls1 += s[nf][2] + s[nf][3];
        }
        ls0 += __shfl_xor_sync(0xffffffffu, ls0, 1);
        ls0 += __shfl_xor_sync(0xffffffffu, ls0, 2);
        ls1 += __shfl_xor_sync(0xffffffffu, ls1, 1);
        ls1 += __shfl_xor_sync(0xffffffffu, ls1, 2);
        l0 = l0 * a0 + ls0;
        l1 = l1 * a1 + ls1;
        m0 = mn0; m1 = mn1;
#pragma unroll
        for (int nf = 0; nf < 8; nf++) {
            o[nf][0] *= a0; o[nf][1] *= a0;
            o[nf][2] *= a1; o[nf][3] *= a1;
        }

#pragma unroll
        for (int kg = 0; kg < 4; kg++) {
            uint32_t ph[4], pl[4];
            split2(s[2 * kg][0], s[2 * kg][1], ph[0], pl[0]);
            split2(s[2 * kg][2], s[2 * kg][3], ph[1], pl[1]);
            split2(s[2 * kg + 1][0], s[2 * kg + 1][1], ph[2], pl[2]);
            split2(s[2 * kg + 1][2], s[2 * kg + 1][3], ph[3], pl[3]);
#pragma unroll
            for (int np = 0; np < 4; np++) {
                int krow = kg * 16 + (lane & 15);
                int nc = np * 2 + (lane >> 4);
                uint32_t off = (uint32_t)(krow * 64 + ((nc ^ (krow & 7)) << 3)) * 2;
                uint32_t rh[4], rl[4];
                ldsm4t(rh, sb + FV_H * 2 + off);
                ldsm4t(rl, sb + FV_L * 2 + off);
                uint32_t vh0[2] = {rh[0], rh[1]}, vh1[2] = {rh[2], rh[3]};
                uint32_t vl0[2] = {rl[0], rl[1]}, vl1[2] = {rl[2], rl[3]};
                mma16816(o[np * 2], ph, vh0);
                mma16816(o[np * 2], ph, vl0);
                mma16816(o[np * 2], pl, vh0);
                mma16816(o[np * 2 + 1], ph, vh1);
                mma16816(o[np * 2 + 1], ph, vl1);
                mma16816(o[np * 2 + 1], pl, vh1);
            }
        }
        __syncthreads();
    }

    float li0 = 1.0f / l0, li1 = 1.0f / l1;
    int r0 = wid * 16 + (lane >> 2);
    size_t row0 = (qrow0 + r0) * DMODEL + hoff + (lane & 3) * 2;
    size_t row1 = (qrow0 + r0 + 8) * DMODEL + hoff + (lane & 3) * 2;
#pragma unroll
    for (int nf = 0; nf < 8; nf++) {
        uint32_t hi, lo;
        split2(o[nf][0] * li0, o[nf][1] * li0, hi, lo);
        *(uint32_t*)(Oh + row0 + nf * 8) = hi;
        *(uint32_t*)(Ol + row0 + nf * 8) = lo;
        split2(o[nf][2] * li1, o[nf][3] * li1, hi, lo);
        *(uint32_t*)(Oh + row1 + nf * 8) = hi;
        *(uint32_t*)(Ol + row1 + nf * 8) = lo;
    }
}

// ---------------- orchestration -------------------------------------------
extern "C" void kernel_launch(void* const* d_in, const int* in_sizes, int n_in,
                              void* d_out, int out_size) {
    (void)in_sizes; (void)n_in; (void)out_size;
    const float* x_in    = (const float*)d_in[0];
    const int*   lengths = (const int*)d_in[1];
    const float* Wq = (const float*)d_in[2];
    const float* Wk = (const float*)d_in[3];
    const float* Wv = (const float*)d_in[4];
    const float* Wo = (const float*)d_in[5];
    const float* ln1g = (const float*)d_in[6];
    const float* ln1b = (const float*)d_in[7];
    const float* ln2g = (const float*)d_in[8];
    const float* ln2b = (const float*)d_in[9];
    const float* w1 = (const float*)d_in[10];
    const float* b1 = (const float*)d_in[11];
    const float* w2 = (const float*)d_in[12];
    const float* b2 = (const float*)d_in[13];

    float* px;
    bf16 *phh, *phl, *pqkvh, *pqkvl, *pfh, *pfl, *pwh, *pwl;
    cudaGetSymbolAddress((void**)&px, g_x);
    cudaGetSymbolAddress((void**)&phh, g_hh);
    cudaGetSymbolAddress((void**)&phl, g_hl);
    cudaGetSymbolAddress((void**)&pqkvh, g_qkvh);
    cudaGetSymbolAddress((void**)&pqkvl, g_qkvl);
    cudaGetSymbolAddress((void**)&pfh, g_fh);
    cudaGetSymbolAddress((void**)&pfl, g_fl);
    cudaGetSymbolAddress((void**)&pwh, g_wh);
    cudaGetSymbolAddress((void**)&pwl, g_wl);

    cudaFuncSetAttribute(k_fattn, cudaFuncAttributeMaxDynamicSharedMemorySize, FSMEM);
    cudaFuncSetAttribute(k_mm<false, false, false, true>,
                         cudaFuncAttributeMaxDynamicSharedMemorySize, GSMEM);
    cudaFuncSetAttribute(k_mm<false, false, true, false>,
                         cudaFuncAttributeMaxDynamicSharedMemorySize, GSMEM);
    cudaFuncSetAttribute(k_mm<true, true, false, true>,
                         cudaFuncAttributeMaxDynamicSharedMemorySize, GSMEM);
    cudaFuncSetAttribute(k_mm<true, false, true, false>,
                         cudaFuncAttributeMaxDynamicSharedMemorySize, GSMEM);

    // launch #1: combined weight split  (#2: pos, #3: ln, #4: QKV mm,
    // #5: attn, #6: WO mm  -> ncu -s 5 -c 1 captures the WO GEMM)
    k_wsplit<<<(WTOT / 4 + 255) / 256, 256>>>(Wq, Wk, Wv, Wo, w1, w2, pwh, pwl);
    k_pos<<<(BL * DMODEL) / 256, 256>>>(x_in, px);

    dim3 gQKV(QKVS / GBN, BL / GBM);   // (12, 64)
    dim3 gD(DMODEL / GBN, BL / GBM);   // (4, 64)
    dim3 gF(DFF / GBN, BL / GBM);      // (16, 64)
    dim3 gA(SEQL / FBR, NHEAD, BATCH);

    for (int layer = 0; layer < NLAYER; layer++) {
        const bf16* qkvh = pwh + OFF_QKV + (size_t)layer * DMODEL * QKVS;
        const bf16* qkvl = pwl + OFF_QKV + (size_t)layer * DMODEL * QKVS;
        const bf16* woh  = pwh + OFF_WO + (size_t)layer * DMODEL * DMODEL;
        const bf16* wol  = pwl + OFF_WO + (size_t)layer * DMODEL * DMODEL;
        const bf16* w1h  = pwh + OFF_W1 + (size_t)layer * DMODEL * DFF;
        const bf16* w1l  = pwl + OFF_W1 + (size_t)layer * DMODEL * DFF;
        const bf16* w2h  = pwh + OFF_W2 + (size_t)layer * DFF * DMODEL;
        const bf16* w2l  = pwl + OFF_W2 + (size_t)layer * DFF * DMODEL;

        k_ln<<<BL, 128>>>(px, ln1g + (size_t)layer * DMODEL, ln1b + (size_t)layer * DMODEL,
                          phh, phl);
        k_mm<false, false, false, true><<<gQKV, 256, GSMEM>>>(
            phh, phl, qkvh, qkvl, nullptr, nullptr, nullptr, pqkvh, pqkvl,
            BL, QKVS, DMODEL);
        k_fattn<<<gA, 256, FSMEM>>>(pqkvh, pqkvl, lengths, phh, phl);
        k_mm<false, false, true, false><<<gD, 256, GSMEM>>>(
            phh, phl, woh, wol, nullptr, px, px, nullptr, nullptr, BL, DMODEL, DMODEL);

        k_ln<<<BL, 128>>>(px, ln2g + (size_t)layer * DMODEL, ln2b + (size_t)layer * DMODEL,
                          phh, phl);
        k_mm<true, true, false, true><<<gF, 256, GSMEM>>>(
            phh, phl, w1h, w1l, b1 + (size_t)layer * DFF, nullptr,
            nullptr, pfh, pfl, BL, DFF, DMODEL);
        float* dst = (layer == NLAYER - 1) ? (float*)d_out : px;
        k_mm<true, false, true, false><<<gD, 256, GSMEM>>>(
            pfh, pfl, w2h, w2l, b2 + (size_t)layer * DMODEL, px,
            dst, nullptr, nullptr, BL, DMODEL, DFF);
    }
}